// round 9
// baseline (speedup 1.0000x reference)
#include <cuda_runtime.h>
#include <cuda_bf16.h>
#include <float.h>

#define PP  64
#define NN  2048
#define M1  512
#define M2  128
#define KNB 32

typedef unsigned long long u64;

// ---- output layout (float32, concatenated in reference return order) ----
#define OFF_XG     0            // [64,768]
#define OFF_POSG   49152        // [64,3]
#define OFF_BATCHG 49344        // [64]
#define OFF_X2     49408        // [8192,384]
#define OFF_Q2     3195136      // [8192,3]
#define OFF_BATCH2 3219712      // [8192]
#define OFF_VMIN   3227904      // [64,3]
#define OFF_DIFF   3228096      // [64]

// ---- scratch (device globals; no allocation allowed) ----
__device__ float g_pn[PP * NN * 3];
__device__ float g_q1[PP * M1 * 3];
__device__ float g_q2[PP * M2 * 3];
__device__ int   g_nidx1[PP * M1 * KNB];
__device__ int   g_nidx2[PP * M2 * KNB];
__device__ float g_x1[PP * M1 * 128];

// Exact (non-contracted) squared distance, (dx^2 + dy^2) + dz^2 order.
__device__ __forceinline__ float d2_exact(float ax, float ay, float az,
                                          float bx, float by, float bz) {
    float dx = ax - bx, dy = ay - by, dz = az - bz;
    float s = __fmul_rn(dx, dx);
    s = __fadd_rn(s, __fmul_rn(dy, dy));
    s = __fadd_rn(s, __fmul_rn(dz, dz));
    return s;
}

// ---- packed f32x2 helpers (Blackwell FFMA2) ----
__device__ __forceinline__ u64 fma2(u64 a, u64 b, u64 c) {
    u64 d;
    asm("fma.rn.f32x2 %0, %1, %2, %3;" : "=l"(d) : "l"(a), "l"(b), "l"(c));
    return d;
}
__device__ __forceinline__ u64 dup2(float w) {
    u64 r;
    asm("mov.b64 %0, {%1, %1};" : "=l"(r) : "f"(w));
    return r;
}
__device__ __forceinline__ float2 unpk(u64 v) {
    float2 f;
    asm("mov.b64 {%0, %1}, %2;" : "=f"(f.x), "=f"(f.y) : "l"(v));
    return f;
}

// ---------------------------------------------------------------------------
__global__ void kinit(float* __restrict__ out) {
    int i = blockIdx.x * blockDim.x + threadIdx.x;
    if (i < 49152) out[OFF_XG + i] = 0.0f;
    if (i < 192)   out[OFF_POSG + i] = 0.0f;
    if (i < 64)    out[OFF_BATCHG + i] = (float)i;
    if (i < 8192)  out[OFF_BATCH2 + i] = (float)(i >> 7);
}

// ---------------------------------------------------------------------------
__global__ void knorm(const float* __restrict__ pos, float* __restrict__ out) {
    __shared__ float sbuf[256];
    __shared__ float smn[3], smx[3];
    __shared__ float sdiff;
    int tid = threadIdx.x, p = blockIdx.x;
    const float* base = pos + (size_t)p * NN * 3;

    float mn[3] = { FLT_MAX,  FLT_MAX,  FLT_MAX};
    float mx[3] = {-FLT_MAX, -FLT_MAX, -FLT_MAX};
    for (int i = tid; i < NN; i += 256) {
        float a = base[i * 3 + 0], b = base[i * 3 + 1], c = base[i * 3 + 2];
        mn[0] = fminf(mn[0], a); mx[0] = fmaxf(mx[0], a);
        mn[1] = fminf(mn[1], b); mx[1] = fmaxf(mx[1], b);
        mn[2] = fminf(mn[2], c); mx[2] = fmaxf(mx[2], c);
    }
    for (int r = 0; r < 6; r++) {
        sbuf[tid] = (r < 3) ? mn[r] : mx[r - 3];
        __syncthreads();
        for (int s = 128; s > 0; s >>= 1) {
            if (tid < s) {
                sbuf[tid] = (r < 3) ? fminf(sbuf[tid], sbuf[tid + s])
                                    : fmaxf(sbuf[tid], sbuf[tid + s]);
            }
            __syncthreads();
        }
        if (tid == 0) { if (r < 3) smn[r] = sbuf[0]; else smx[r - 3] = sbuf[0]; }
        __syncthreads();
    }
    if (tid == 0) {
        float d = fmaxf(fmaxf(smx[0] - smn[0], smx[1] - smn[1]), smx[2] - smn[2]);
        sdiff = d;
        out[OFF_VMIN + p * 3 + 0] = smn[0];
        out[OFF_VMIN + p * 3 + 1] = smn[1];
        out[OFF_VMIN + p * 3 + 2] = smn[2];
        out[OFF_DIFF + p] = d;
    }
    __syncthreads();
    float dv = sdiff;
    for (int o = tid; o < NN * 3; o += 256) {
        int d = o % 3;
        g_pn[(size_t)p * NN * 3 + o] = __fdiv_rn(base[o] - smn[d], dv);
    }
}

// ---------------------------------------------------------------------------
// FPS: fused update+argmax, 1 syncthreads/iter; warp argmax via 2x REDUX.
// ---------------------------------------------------------------------------
template <int NSRC, int M, int STAGE>
__global__ __launch_bounds__(256) void kfps() {
    const float* pts = (STAGE == 1) ? g_pn : g_q1;
    float* qout      = (STAGE == 1) ? g_q1 : g_q2;
    const int PT = NSRC / 256;

    __shared__ float sx[NSRC], sy[NSRC], sz[NSRC];
    __shared__ u64 wred[2][8];
    int tid = threadIdx.x, p = blockIdx.x;
    int lane = tid & 31, wid = tid >> 5;
    const float* base = pts + (size_t)p * NSRC * 3;

    float px[PT], py[PT], pz[PT], dd[PT];
    #pragma unroll
    for (int t = 0; t < PT; t++) {
        int i = tid + t * 256;
        float a = base[i * 3 + 0], b = base[i * 3 + 1], c = base[i * 3 + 2];
        sx[i] = a; sy[i] = b; sz[i] = c;
        px[t] = a; py[t] = b; pz[t] = c;
        dd[t] = FLT_MAX;
    }
    __syncthreads();
    float cx = sx[0], cy = sy[0], cz = sz[0];
    if (tid == 0) {
        qout[(size_t)p * M * 3 + 0] = cx;
        qout[(size_t)p * M * 3 + 1] = cy;
        qout[(size_t)p * M * 3 + 2] = cz;
    }

    for (int it = 1; it < M; it++) {
        unsigned bb = 0, binv = 0;   // d2 bits, ~idx
        #pragma unroll
        for (int t = 0; t < PT; t++) {
            float nd = d2_exact(px[t], py[t], pz[t], cx, cy, cz);
            dd[t] = fminf(dd[t], nd);
            unsigned db = __float_as_uint(dd[t]);
            if (db > bb) { bb = db; binv = ~(unsigned)(tid + t * 256); }
        }
        unsigned gmax = __reduce_max_sync(0xffffffffu, bb);
        unsigned cand = (bb == gmax) ? binv : 0u;
        unsigned ginv = __reduce_max_sync(0xffffffffu, cand);
        if (lane == 0) wred[it & 1][wid] = ((u64)gmax << 32) | (u64)ginv;
        __syncthreads();
        u64 m = wred[it & 1][0];
        #pragma unroll
        for (int w = 1; w < 8; w++) {
            u64 o = wred[it & 1][w];
            m = (o > m) ? o : m;
        }
        unsigned j = ~(unsigned)(m & 0xFFFFFFFFu);
        cx = sx[j]; cy = sy[j]; cz = sz[j];
        if (tid == 0) {
            qout[((size_t)p * M + it) * 3 + 0] = cx;
            qout[((size_t)p * M + it) * 3 + 1] = cy;
            qout[((size_t)p * M + it) * 3 + 2] = cz;
        }
    }
}

// ---------------------------------------------------------------------------
// Radius neighbors: ballot-compaction + REDUX argmin selection.
// ---------------------------------------------------------------------------
template <int NSRC, int M, int STAGE, int CAP>
__global__ __launch_bounds__(256) void kneigh() {
    const float* src  = (STAGE == 1) ? g_pn : g_q1;
    const float* qsrc = (STAGE == 1) ? g_q1 : g_q2;
    int* nidx         = (STAGE == 1) ? g_nidx1 : g_nidx2;
    const float r2    = (STAGE == 1) ? (float)(0.15 * 0.15) : (float)(0.3 * 0.3);

    extern __shared__ __align__(16) char dynbuf[];
    float4* spts = (float4*)dynbuf;                         // [NSRC]
    unsigned short* cand = (unsigned short*)(spts + NSRC);  // [8][CAP]

    int tid = threadIdx.x;
    int lane = tid & 31, w = tid >> 5;
    int tilesPerPatch = M / 16;
    int p    = blockIdx.x / tilesPerPatch;
    int tile = blockIdx.x % tilesPerPatch;
    const float* base = src + (size_t)p * NSRC * 3;

    for (int i = tid; i < NSRC; i += 256) {
        spts[i] = make_float4(base[i * 3 + 0], base[i * 3 + 1], base[i * 3 + 2], 0.0f);
    }
    __syncthreads();

    unsigned short* mycand = cand + (size_t)w * CAP;
    unsigned lmask = (1u << lane) - 1u;

    for (int g = 0; g < 2; g++) {
        int center = p * M + tile * 16 + g * 8 + w;
        float qx = qsrc[center * 3 + 0];
        float qy = qsrc[center * 3 + 1];
        float qz = qsrc[center * 3 + 2];

        int cnt = 0;
        for (int i = lane; i < NSRC; i += 32) {
            float4 pt = spts[i];
            float d2 = d2_exact(pt.x, pt.y, pt.z, qx, qy, qz);
            bool in = (d2 <= r2);
            unsigned mk = __ballot_sync(0xffffffffu, in);
            if (in) {
                int pos = cnt + __popc(mk & lmask);
                if (pos < CAP) mycand[pos] = (unsigned short)i;
            }
            cnt += __popc(mk);
        }

        if (cnt <= 32) {
            int v = (lane < cnt) ? (int)mycand[lane] : -1;
            nidx[center * KNB + lane] = v;
        } else if (cnt <= CAP) {
            unsigned last_d2 = 0, last_idx = 0;
            for (int k = 0; k < KNB; k++) {
                unsigned bd2 = 0xFFFFFFFFu, bidx = 0xFFFFFFFFu;
                for (int i = lane; i < cnt; i += 32) {
                    unsigned idx = mycand[i];
                    float4 pt = spts[idx];
                    float d2 = d2_exact(pt.x, pt.y, pt.z, qx, qy, qz);
                    unsigned db = __float_as_uint(d2);
                    bool ok = (k == 0) || (db > last_d2) ||
                              (db == last_d2 && idx > last_idx);
                    if (ok && db < bd2) { bd2 = db; bidx = idx; }
                }
                unsigned gmin = __reduce_min_sync(0xffffffffu, bd2);
                unsigned cd = (bd2 == gmin) ? bidx : 0xFFFFFFFFu;
                unsigned gidx = __reduce_min_sync(0xffffffffu, cd);
                if (lane == 0) nidx[center * KNB + k] = (int)gidx;
                last_d2 = gmin; last_idx = gidx;
            }
        } else {
            unsigned last_d2 = 0, last_idx = 0;
            for (int k = 0; k < KNB; k++) {
                unsigned bd2 = 0xFFFFFFFFu, bidx = 0xFFFFFFFFu;
                for (int i = lane; i < NSRC; i += 32) {
                    float4 pt = spts[i];
                    float d2 = d2_exact(pt.x, pt.y, pt.z, qx, qy, qz);
                    if (d2 <= r2) {
                        unsigned db = __float_as_uint(d2);
                        unsigned idx = (unsigned)i;
                        bool ok = (k == 0) || (db > last_d2) ||
                                  (db == last_d2 && idx > last_idx);
                        if (ok && db < bd2) { bd2 = db; bidx = idx; }
                    }
                }
                unsigned gmin = __reduce_min_sync(0xffffffffu, bd2);
                unsigned cd = (bd2 == gmin) ? bidx : 0xFFFFFFFFu;
                unsigned gidx = __reduce_min_sync(0xffffffffu, cd);
                if (lane == 0) nidx[center * KNB + k] = (int)gidx;
                last_d2 = gmin; last_idx = gidx;
            }
        }
    }
}

// ---------------------------------------------------------------------------
// Stage-1 MLP: feat[32,6] -> 64 -> 128, max over valid K.
// 256 threads = 4 groups of 64; 8 centers/block (2 rounds of 4).
// Layer-1: W1a rows in registers (center-invariant), 4ch x 8k per thread.
// Layer-2: 8ch x 8k per thread, weights from shared.
// ---------------------------------------------------------------------------
__global__ __launch_bounds__(256) void kmlp1(
    const float* __restrict__ W1a, const float* __restrict__ b1a,
    const float* __restrict__ W1b, const float* __restrict__ b1b) {
    extern __shared__ __align__(16) float sm1[];
    float* sWb = sm1;                  // 64*128
    float* sbb = sWb + 64 * 128;       // 128
    float* sfeatA = sbb + 128;         // [4][6*32]
    float* sh1A   = sfeatA + 4 * 6 * 32;  // [4][64*32]
    __shared__ int   sj[4][32];
    __shared__ float sq[4][3];

    int tid = threadIdx.x;
    int g = tid >> 6, t = tid & 63;
    float* sfeat = sfeatA + g * 6 * 32;
    float* sh1   = sh1A + g * 64 * 32;

    for (int i = tid; i < 64 * 128; i += 256) sWb[i] = W1b[i];
    if (tid < 128) sbb[tid] = b1b[tid];

    // layer-1 mapping: 4ch x 8k
    int kg1 = t & 3, k1 = kg1 * 8;
    int c1  = (t >> 2) * 4;            // 0..60
    float4 w1[6];
    #pragma unroll
    for (int f = 0; f < 6; f++) w1[f] = __ldg((const float4*)&W1a[f * 64 + c1]);
    float4 b1 = __ldg((const float4*)&b1a[c1]);

    // layer-2 mapping: 8ch x 8k
    int kg = t & 3, k0 = kg * 8;
    int c0 = (t >> 2) * 8;             // 0..120

    for (int cc = 0; cc < 2; cc++) {
        __syncthreads();
        int center = blockIdx.x * 8 + cc * 4 + g;
        int p = center >> 9;
        if (t < 32) sj[g][t] = g_nidx1[center * KNB + t];
        if (t < 3)  sq[g][t] = g_q1[center * 3 + t];
        __syncthreads();

        for (int o = t; o < 192; o += 64) {
            int k = o & 31, f = o >> 5;
            int j = sj[g][k];
            float v = 0.0f;
            if (j >= 0) {
                int d = (f < 3) ? f : (f - 3);
                float pj = g_pn[((size_t)p * NN + j) * 3 + d];
                v = (f < 3) ? pj : (pj - sq[g][d]);
            }
            sfeat[f * 32 + k] = v;
        }
        __syncthreads();

        // ---- layer 1: 6 -> 64, 4ch x 8k ----
        {
            u64 a1[16];   // [ci][q]  (q: pairs of k)
            float bia[4] = {b1.x, b1.y, b1.z, b1.w};
            #pragma unroll
            for (int ci = 0; ci < 4; ci++) {
                u64 bb = dup2(bia[ci]);
                a1[ci * 4 + 0] = bb; a1[ci * 4 + 1] = bb;
                a1[ci * 4 + 2] = bb; a1[ci * 4 + 3] = bb;
            }
            #pragma unroll
            for (int f = 0; f < 6; f++) {
                const ulonglong2* hp = (const ulonglong2*)&sfeat[f * 32 + k1];
                ulonglong2 ha = hp[0], hb = hp[1];
                float wf[4] = {w1[f].x, w1[f].y, w1[f].z, w1[f].w};
                #pragma unroll
                for (int ci = 0; ci < 4; ci++) {
                    u64 w = dup2(wf[ci]);
                    a1[ci * 4 + 0] = fma2(ha.x, w, a1[ci * 4 + 0]);
                    a1[ci * 4 + 1] = fma2(ha.y, w, a1[ci * 4 + 1]);
                    a1[ci * 4 + 2] = fma2(hb.x, w, a1[ci * 4 + 2]);
                    a1[ci * 4 + 3] = fma2(hb.y, w, a1[ci * 4 + 3]);
                }
            }
            #pragma unroll
            for (int ci = 0; ci < 4; ci++) {
                float2 f0 = unpk(a1[ci * 4 + 0]);
                float2 f1 = unpk(a1[ci * 4 + 1]);
                float2 f2 = unpk(a1[ci * 4 + 2]);
                float2 f3 = unpk(a1[ci * 4 + 3]);
                float4 lo, hi;
                lo.x = fmaxf(f0.x, 0.0f); lo.y = fmaxf(f0.y, 0.0f);
                lo.z = fmaxf(f1.x, 0.0f); lo.w = fmaxf(f1.y, 0.0f);
                hi.x = fmaxf(f2.x, 0.0f); hi.y = fmaxf(f2.y, 0.0f);
                hi.z = fmaxf(f3.x, 0.0f); hi.w = fmaxf(f3.y, 0.0f);
                *(float4*)&sh1[(c1 + ci) * 32 + k1]     = lo;
                *(float4*)&sh1[(c1 + ci) * 32 + k1 + 4] = hi;
            }
        }
        __syncthreads();

        // ---- layer 2: 64 -> 128, 8ch x 8k ----
        {
            u64 acc[32];
            #pragma unroll
            for (int q = 0; q < 32; q++) acc[q] = 0ull;
            #pragma unroll 2
            for (int i = 0; i < 64; i++) {
                float4 wA = *(const float4*)&sWb[i * 128 + c0];
                float4 wB = *(const float4*)&sWb[i * 128 + c0 + 4];
                const ulonglong2* hp = (const ulonglong2*)&sh1[i * 32 + k0];
                ulonglong2 ha = hp[0], hb = hp[1];
                float wf[8] = {wA.x, wA.y, wA.z, wA.w, wB.x, wB.y, wB.z, wB.w};
                #pragma unroll
                for (int ci = 0; ci < 8; ci++) {
                    u64 w = dup2(wf[ci]);
                    acc[ci * 4 + 0] = fma2(ha.x, w, acc[ci * 4 + 0]);
                    acc[ci * 4 + 1] = fma2(ha.y, w, acc[ci * 4 + 1]);
                    acc[ci * 4 + 2] = fma2(hb.x, w, acc[ci * 4 + 2]);
                    acc[ci * 4 + 3] = fma2(hb.y, w, acc[ci * 4 + 3]);
                }
            }
            float4 bA = *(const float4*)&sbb[c0];
            float4 bB = *(const float4*)&sbb[c0 + 4];
            float bias[8] = {bA.x, bA.y, bA.z, bA.w, bB.x, bB.y, bB.z, bB.w};
            #pragma unroll
            for (int ci = 0; ci < 8; ci++) {
                float b = bias[ci];
                float m = -FLT_MAX;
                #pragma unroll
                for (int qq = 0; qq < 4; qq++) {
                    float2 f = unpk(acc[ci * 4 + qq]);
                    if (sj[g][k0 + 2 * qq + 0] >= 0) m = fmaxf(m, fmaxf(f.x + b, 0.0f));
                    if (sj[g][k0 + 2 * qq + 1] >= 0) m = fmaxf(m, fmaxf(f.y + b, 0.0f));
                }
                m = fmaxf(m, __shfl_xor_sync(0xffffffffu, m, 1));
                m = fmaxf(m, __shfl_xor_sync(0xffffffffu, m, 2));
                if (kg == 0) g_x1[(size_t)center * 128 + c0 + ci] = m;
            }
        }
    }
}

// ---------------------------------------------------------------------------
// Stage-2 MLP: feat[32,131] -> 256 -> 384, max over valid K.
// 256 threads = 2 groups of 128, one center each. Layer A: 8ch x 8k (1 pass).
// Layer B: pass0 8ch x 8k (ch 0..255), pass1 4ch x 8k (ch 256..383).
// ---------------------------------------------------------------------------
__global__ __launch_bounds__(256) void kmlp2(
    const float* __restrict__ W2a, const float* __restrict__ b2a,
    const float* __restrict__ W2b, const float* __restrict__ b2b,
    float* __restrict__ out) {
    extern __shared__ __align__(16) float smem2[];
    int tid = threadIdx.x;
    int grp = tid >> 7, t = tid & 127;
    float* sfeat = smem2 + grp * (131 * 32 + 256 * 32);   // [131][32]
    float* sh1   = sfeat + 131 * 32;                      // [256][32]
    __shared__ int   sj[2][32];
    __shared__ float sq[2][3];

    int center = blockIdx.x * 2 + grp;
    int p = center >> 7;
    if (t < 32) sj[grp][t] = g_nidx2[center * KNB + t];
    if (t < 3) {
        float qv = g_q2[center * 3 + t];
        sq[grp][t] = qv;
        out[OFF_Q2 + center * 3 + t] = qv;
    }
    __syncthreads();

    for (int o = t; o < 131 * 32; o += 128) {
        int k = o & 31, i = o >> 5;
        int j = sj[grp][k];
        float v = 0.0f;
        if (j >= 0) {
            if (i < 128) v = g_x1[((size_t)p * M1 + j) * 128 + i];
            else         v = g_q1[((size_t)p * M1 + j) * 3 + (i - 128)] - sq[grp][i - 128];
        }
        sfeat[i * 32 + k] = v;
    }
    __syncthreads();

    int kg = t & 3, k0 = kg * 8;
    int c0 = (t >> 2) * 8;             // 0..248

    // ---- layer A: 131 -> 256, 8ch x 8k ----
    {
        u64 acc[32];
        #pragma unroll
        for (int q = 0; q < 32; q++) acc[q] = 0ull;
        #pragma unroll 2
        for (int i = 0; i < 131; i++) {
            float4 wA = __ldg((const float4*)&W2a[i * 256 + c0]);
            float4 wB = __ldg((const float4*)&W2a[i * 256 + c0 + 4]);
            const ulonglong2* hp = (const ulonglong2*)&sfeat[i * 32 + k0];
            ulonglong2 ha = hp[0], hb = hp[1];
            float wf[8] = {wA.x, wA.y, wA.z, wA.w, wB.x, wB.y, wB.z, wB.w};
            #pragma unroll
            for (int ci = 0; ci < 8; ci++) {
                u64 w = dup2(wf[ci]);
                acc[ci * 4 + 0] = fma2(ha.x, w, acc[ci * 4 + 0]);
                acc[ci * 4 + 1] = fma2(ha.y, w, acc[ci * 4 + 1]);
                acc[ci * 4 + 2] = fma2(hb.x, w, acc[ci * 4 + 2]);
                acc[ci * 4 + 3] = fma2(hb.y, w, acc[ci * 4 + 3]);
            }
        }
        float4 bA = __ldg((const float4*)&b2a[c0]);
        float4 bB = __ldg((const float4*)&b2a[c0 + 4]);
        float bias[8] = {bA.x, bA.y, bA.z, bA.w, bB.x, bB.y, bB.z, bB.w};
        #pragma unroll
        for (int ci = 0; ci < 8; ci++) {
            float b = bias[ci];
            float2 f0 = unpk(acc[ci * 4 + 0]);
            float2 f1 = unpk(acc[ci * 4 + 1]);
            float2 f2 = unpk(acc[ci * 4 + 2]);
            float2 f3 = unpk(acc[ci * 4 + 3]);
            float4 lo, hi;
            lo.x = fmaxf(f0.x + b, 0.0f); lo.y = fmaxf(f0.y + b, 0.0f);
            lo.z = fmaxf(f1.x + b, 0.0f); lo.w = fmaxf(f1.y + b, 0.0f);
            hi.x = fmaxf(f2.x + b, 0.0f); hi.y = fmaxf(f2.y + b, 0.0f);
            hi.z = fmaxf(f3.x + b, 0.0f); hi.w = fmaxf(f3.y + b, 0.0f);
            *(float4*)&sh1[(c0 + ci) * 32 + k0]     = lo;
            *(float4*)&sh1[(c0 + ci) * 32 + k0 + 4] = hi;
        }
    }
    __syncthreads();

    // ---- layer B pass 0: ch 0..255, 8ch x 8k ----
    {
        u64 acc[32];
        #pragma unroll
        for (int q = 0; q < 32; q++) acc[q] = 0ull;
        #pragma unroll 2
        for (int i = 0; i < 256; i++) {
            float4 wA = __ldg((const float4*)&W2b[i * 384 + c0]);
            float4 wB = __ldg((const float4*)&W2b[i * 384 + c0 + 4]);
            const ulonglong2* hp = (const ulonglong2*)&sh1[i * 32 + k0];
            ulonglong2 ha = hp[0], hb = hp[1];
            float wf[8] = {wA.x, wA.y, wA.z, wA.w, wB.x, wB.y, wB.z, wB.w};
            #pragma unroll
            for (int ci = 0; ci < 8; ci++) {
                u64 w = dup2(wf[ci]);
                acc[ci * 4 + 0] = fma2(ha.x, w, acc[ci * 4 + 0]);
                acc[ci * 4 + 1] = fma2(ha.y, w, acc[ci * 4 + 1]);
                acc[ci * 4 + 2] = fma2(hb.x, w, acc[ci * 4 + 2]);
                acc[ci * 4 + 3] = fma2(hb.y, w, acc[ci * 4 + 3]);
            }
        }
        float4 bA = __ldg((const float4*)&b2b[c0]);
        float4 bB = __ldg((const float4*)&b2b[c0 + 4]);
        float bias[8] = {bA.x, bA.y, bA.z, bA.w, bB.x, bB.y, bB.z, bB.w};
        #pragma unroll
        for (int ci = 0; ci < 8; ci++) {
            float b = bias[ci];
            float m = -FLT_MAX;
            #pragma unroll
            for (int qq = 0; qq < 4; qq++) {
                float2 f = unpk(acc[ci * 4 + qq]);
                if (sj[grp][k0 + 2 * qq + 0] >= 0) m = fmaxf(m, fmaxf(f.x + b, 0.0f));
                if (sj[grp][k0 + 2 * qq + 1] >= 0) m = fmaxf(m, fmaxf(f.y + b, 0.0f));
            }
            m = fmaxf(m, __shfl_xor_sync(0xffffffffu, m, 1));
            m = fmaxf(m, __shfl_xor_sync(0xffffffffu, m, 2));
            if (kg == 0) out[OFF_X2 + (size_t)center * 384 + c0 + ci] = m;
        }
    }

    // ---- layer B pass 1: ch 256..383, 4ch x 8k (all threads active) ----
    {
        int c1 = 256 + (t >> 2) * 4;   // 256..380
        u64 acc[16];
        #pragma unroll
        for (int q = 0; q < 16; q++) acc[q] = 0ull;
        #pragma unroll 4
        for (int i = 0; i < 256; i++) {
            float4 w4 = __ldg((const float4*)&W2b[i * 384 + c1]);
            const ulonglong2* hp = (const ulonglong2*)&sh1[i * 32 + k0];
            ulonglong2 ha = hp[0], hb = hp[1];
            u64 w0 = dup2(w4.x), w1 = dup2(w4.y), w2 = dup2(w4.z), w3 = dup2(w4.w);
            acc[0]  = fma2(ha.x, w0, acc[0]);  acc[1]  = fma2(ha.y, w0, acc[1]);
            acc[2]  = fma2(hb.x, w0, acc[2]);  acc[3]  = fma2(hb.y, w0, acc[3]);
            acc[4]  = fma2(ha.x, w1, acc[4]);  acc[5]  = fma2(ha.y, w1, acc[5]);
            acc[6]  = fma2(hb.x, w1, acc[6]);  acc[7]  = fma2(hb.y, w1, acc[7]);
            acc[8]  = fma2(ha.x, w2, acc[8]);  acc[9]  = fma2(ha.y, w2, acc[9]);
            acc[10] = fma2(hb.x, w2, acc[10]); acc[11] = fma2(hb.y, w2, acc[11]);
            acc[12] = fma2(ha.x, w3, acc[12]); acc[13] = fma2(ha.y, w3, acc[13]);
            acc[14] = fma2(hb.x, w3, acc[14]); acc[15] = fma2(hb.y, w3, acc[15]);
        }
        float4 b4 = __ldg((const float4*)&b2b[c1]);
        float bias[4] = {b4.x, b4.y, b4.z, b4.w};
        #pragma unroll
        for (int ci = 0; ci < 4; ci++) {
            float b = bias[ci];
            float m = -FLT_MAX;
            #pragma unroll
            for (int qq = 0; qq < 4; qq++) {
                float2 f = unpk(acc[ci * 4 + qq]);
                if (sj[grp][k0 + 2 * qq + 0] >= 0) m = fmaxf(m, fmaxf(f.x + b, 0.0f));
                if (sj[grp][k0 + 2 * qq + 1] >= 0) m = fmaxf(m, fmaxf(f.y + b, 0.0f));
            }
            m = fmaxf(m, __shfl_xor_sync(0xffffffffu, m, 1));
            m = fmaxf(m, __shfl_xor_sync(0xffffffffu, m, 2));
            if (kg == 0) out[OFF_X2 + (size_t)center * 384 + c1 + ci] = m;
        }
    }
}

// ---------------------------------------------------------------------------
// Stage-3 MLP: feat[387] -> 512 -> 768; 16 centers/block, 256 threads.
// Layer A: 8ch x 4cen single pass. Layer B: 8ch pass (0..511) + 4ch pass.
// ---------------------------------------------------------------------------
__global__ __launch_bounds__(256) void kmlp3(
    const float* __restrict__ W3a, const float* __restrict__ b3a,
    const float* __restrict__ W3b, const float* __restrict__ b3b,
    float* __restrict__ out) {
    extern __shared__ __align__(16) char smem3[];
    float* sfeat = (float*)smem3;          // [387][16]
    float* sh1   = sfeat + 387 * 16;       // [512][16]
    int t = threadIdx.x;
    int base = blockIdx.x * 16;
    int p = base >> 7;

    for (int o = t; o < 387 * 16; o += 256) {
        int cen = o & 15, i = o >> 4;
        int center = base + cen;
        float v = (i < 384) ? out[OFF_X2 + (size_t)center * 384 + i]
                            : out[OFF_Q2 + center * 3 + (i - 384)];
        sfeat[i * 16 + cen] = v;
    }
    __syncthreads();

    int eg = t & 3, e0 = eg * 4;
    int c0 = (t >> 2) * 8;                  // 0..504

    // ---- layer A: 387 -> 512, 8ch x 4cen, single pass ----
    {
        u64 acc[16];
        #pragma unroll
        for (int q = 0; q < 16; q++) acc[q] = 0ull;
        #pragma unroll 2
        for (int i = 0; i < 387; i++) {
            float4 wA = __ldg((const float4*)&W3a[i * 512 + c0]);
            float4 wB = __ldg((const float4*)&W3a[i * 512 + c0 + 4]);
            ulonglong2 h = *(const ulonglong2*)&sfeat[i * 16 + e0];
            float wf[8] = {wA.x, wA.y, wA.z, wA.w, wB.x, wB.y, wB.z, wB.w};
            #pragma unroll
            for (int ci = 0; ci < 8; ci++) {
                u64 w = dup2(wf[ci]);
                acc[ci * 2 + 0] = fma2(h.x, w, acc[ci * 2 + 0]);
                acc[ci * 2 + 1] = fma2(h.y, w, acc[ci * 2 + 1]);
            }
        }
        float4 bA = __ldg((const float4*)&b3a[c0]);
        float4 bB = __ldg((const float4*)&b3a[c0 + 4]);
        float bias[8] = {bA.x, bA.y, bA.z, bA.w, bB.x, bB.y, bB.z, bB.w};
        #pragma unroll
        for (int ci = 0; ci < 8; ci++) {
            float b = bias[ci];
            float2 f0 = unpk(acc[ci * 2 + 0]);
            float2 f1 = unpk(acc[ci * 2 + 1]);
            float4 s;
            s.x = fmaxf(f0.x + b, 0.0f); s.y = fmaxf(f0.y + b, 0.0f);
            s.z = fmaxf(f1.x + b, 0.0f); s.w = fmaxf(f1.y + b, 0.0f);
            *(float4*)&sh1[(c0 + ci) * 16 + e0] = s;
        }
    }
    __syncthreads();

    // ---- layer B pass 0: ch 0..511, 8ch x 4cen ----
    {
        u64 acc[16];
        #pragma unroll
        for (int q = 0; q < 16; q++) acc[q] = 0ull;
        #pragma unroll 2
        for (int i = 0; i < 512; i++) {
            float4 wA = __ldg((const float4*)&W3b[i * 768 + c0]);
            float4 wB = __ldg((const float4*)&W3b[i * 768 + c0 + 4]);
            ulonglong2 h = *(const ulonglong2*)&sh1[i * 16 + e0];
            float wf[8] = {wA.x, wA.y, wA.z, wA.w, wB.x, wB.y, wB.z, wB.w};
            #pragma unroll
            for (int ci = 0; ci < 8; ci++) {
                u64 w = dup2(wf[ci]);
                acc[ci * 2 + 0] = fma2(h.x, w, acc[ci * 2 + 0]);
                acc[ci * 2 + 1] = fma2(h.y, w, acc[ci * 2 + 1]);
            }
        }
        float4 bA = __ldg((const float4*)&b3b[c0]);
        float4 bB = __ldg((const float4*)&b3b[c0 + 4]);
        float bias[8] = {bA.x, bA.y, bA.z, bA.w, bB.x, bB.y, bB.z, bB.w};
        #pragma unroll
        for (int ci = 0; ci < 8; ci++) {
            float b = bias[ci];
            float2 f0 = unpk(acc[ci * 2 + 0]);
            float2 f1 = unpk(acc[ci * 2 + 1]);
            float m = fmaxf(fmaxf(f0.x + b, 0.0f), fmaxf(f0.y + b, 0.0f));
            m = fmaxf(m, fmaxf(f1.x + b, 0.0f));
            m = fmaxf(m, fmaxf(f1.y + b, 0.0f));
            m = fmaxf(m, __shfl_xor_sync(0xffffffffu, m, 1));
            m = fmaxf(m, __shfl_xor_sync(0xffffffffu, m, 2));
            if (eg == 0)
                atomicMax((int*)&out[OFF_XG + p * 768 + c0 + ci], __float_as_int(m));
        }
    }

    // ---- layer B pass 1: ch 512..767, 4ch x 4cen (all threads active) ----
    {
        int cb = 512 + (t >> 2) * 4;    // 512..764
        u64 acc[8];
        #pragma unroll
        for (int q = 0; q < 8; q++) acc[q] = 0ull;
        #pragma unroll 4
        for (int i = 0; i < 512; i++) {
            float4 w4 = __ldg((const float4*)&W3b[i * 768 + cb]);
            ulonglong2 h = *(const ulonglong2*)&sh1[i * 16 + e0];
            u64 w0 = dup2(w4.x), w1 = dup2(w4.y), w2 = dup2(w4.z), w3 = dup2(w4.w);
            acc[0] = fma2(h.x, w0, acc[0]); acc[1] = fma2(h.y, w0, acc[1]);
            acc[2] = fma2(h.x, w1, acc[2]); acc[3] = fma2(h.y, w1, acc[3]);
            acc[4] = fma2(h.x, w2, acc[4]); acc[5] = fma2(h.y, w2, acc[5]);
            acc[6] = fma2(h.x, w3, acc[6]); acc[7] = fma2(h.y, w3, acc[7]);
        }
        float4 b4 = __ldg((const float4*)&b3b[cb]);
        float bias[4] = {b4.x, b4.y, b4.z, b4.w};
        #pragma unroll
        for (int ci = 0; ci < 4; ci++) {
            float b = bias[ci];
            float2 f0 = unpk(acc[ci * 2 + 0]);
            float2 f1 = unpk(acc[ci * 2 + 1]);
            float m = fmaxf(fmaxf(f0.x + b, 0.0f), fmaxf(f0.y + b, 0.0f));
            m = fmaxf(m, fmaxf(f1.x + b, 0.0f));
            m = fmaxf(m, fmaxf(f1.y + b, 0.0f));
            m = fmaxf(m, __shfl_xor_sync(0xffffffffu, m, 1));
            m = fmaxf(m, __shfl_xor_sync(0xffffffffu, m, 2));
            if (eg == 0)
                atomicMax((int*)&out[OFF_XG + p * 768 + cb + ci], __float_as_int(m));
        }
    }
}

// ---------------------------------------------------------------------------
extern "C" void kernel_launch(void* const* d_in, const int* in_sizes, int n_in,
                              void* d_out, int out_size) {
    const float* pos = (const float*)d_in[0];
    const float* W1a = (const float*)d_in[2];
    const float* b1a = (const float*)d_in[3];
    const float* W1b = (const float*)d_in[4];
    const float* b1b = (const float*)d_in[5];
    const float* W2a = (const float*)d_in[6];
    const float* b2a = (const float*)d_in[7];
    const float* W2b = (const float*)d_in[8];
    const float* b2b = (const float*)d_in[9];
    const float* W3a = (const float*)d_in[10];
    const float* b3a = (const float*)d_in[11];
    const float* W3b = (const float*)d_in[12];
    const float* b3b = (const float*)d_in[13];
    float* out = (float*)d_out;

    const int CAP1 = 1024, CAP2 = 512;
    const int NEIGH1_SMEM = NN * 16 + 8 * CAP1 * 2;      // 49152
    const int NEIGH2_SMEM = M1 * 16 + 8 * CAP2 * 2;      // 16384
    const int MLP1_SMEM   = (64 * 128 + 128 + 4 * (6 * 32 + 64 * 32)) * 4;  // 69120
    const int MLP2_SMEM   = 2 * (131 * 32 + 256 * 32) * 4;  // 99072
    const int MLP3_SMEM   = (387 * 16 + 512 * 16) * 4;      // 57536
    cudaFuncSetAttribute(kneigh<NN, M1, 1, CAP1>,
                         cudaFuncAttributeMaxDynamicSharedMemorySize, NEIGH1_SMEM);
    cudaFuncSetAttribute(kneigh<M1, M2, 2, CAP2>,
                         cudaFuncAttributeMaxDynamicSharedMemorySize, NEIGH2_SMEM);
    cudaFuncSetAttribute(kmlp1,
                         cudaFuncAttributeMaxDynamicSharedMemorySize, MLP1_SMEM);
    cudaFuncSetAttribute(kmlp2,
                         cudaFuncAttributeMaxDynamicSharedMemorySize, MLP2_SMEM);
    cudaFuncSetAttribute(kmlp3,
                         cudaFuncAttributeMaxDynamicSharedMemorySize, MLP3_SMEM);

    // Launch order: index 3 (kmlp1) is the ncu-profiled launch.
    knorm<<<PP, 256>>>(pos, out);                                        // 0
    kfps<NN, M1, 1><<<PP, 256>>>();                                      // 1
    kneigh<NN, M1, 1, CAP1><<<PP * M1 / 16, 256, NEIGH1_SMEM>>>();       // 2
    kmlp1<<<PP * M1 / 8, 256, MLP1_SMEM>>>(W1a, b1a, W1b, b1b);          // 3 <- profiled
    kfps<M1, M2, 2><<<PP, 256>>>();                                      // 4
    kneigh<M1, M2, 2, CAP2><<<PP * M2 / 16, 256, NEIGH2_SMEM>>>();       // 5
    kmlp2<<<PP * M2 / 2, 256, MLP2_SMEM>>>(W2a, b2a, W2b, b2b, out);     // 6
    kinit<<<192, 256>>>(out);                                            // 7
    kmlp3<<<PP * M2 / 16, 256, MLP3_SMEM>>>(W3a, b3a, W3b, b3b, out);    // 8
}

// round 10
// speedup vs baseline: 1.0278x; 1.0278x over previous
#include <cuda_runtime.h>
#include <cuda_bf16.h>
#include <float.h>

#define PP  64
#define NN  2048
#define M1  512
#define M2  128
#define KNB 32

typedef unsigned long long u64;

// ---- output layout (float32, concatenated in reference return order) ----
#define OFF_XG     0            // [64,768]
#define OFF_POSG   49152        // [64,3]
#define OFF_BATCHG 49344        // [64]
#define OFF_X2     49408        // [8192,384]
#define OFF_Q2     3195136      // [8192,3]
#define OFF_BATCH2 3219712      // [8192]
#define OFF_VMIN   3227904      // [64,3]
#define OFF_DIFF   3228096      // [64]

// ---- scratch (device globals; no allocation allowed) ----
__device__ float g_pn[PP * NN * 3];
__device__ float g_q1[PP * M1 * 3];
__device__ float g_q2[PP * M2 * 3];
__device__ int   g_nidx1[PP * M1 * KNB];
__device__ int   g_nidx2[PP * M2 * KNB];
__device__ float g_x1[PP * M1 * 128];

// Exact (non-contracted) squared distance, (dx^2 + dy^2) + dz^2 order.
__device__ __forceinline__ float d2_exact(float ax, float ay, float az,
                                          float bx, float by, float bz) {
    float dx = ax - bx, dy = ay - by, dz = az - bz;
    float s = __fmul_rn(dx, dx);
    s = __fadd_rn(s, __fmul_rn(dy, dy));
    s = __fadd_rn(s, __fmul_rn(dz, dz));
    return s;
}

// ---- packed f32x2 helpers (Blackwell FFMA2) ----
__device__ __forceinline__ u64 fma2(u64 a, u64 b, u64 c) {
    u64 d;
    asm("fma.rn.f32x2 %0, %1, %2, %3;" : "=l"(d) : "l"(a), "l"(b), "l"(c));
    return d;
}
__device__ __forceinline__ u64 dup2(float w) {
    u64 r;
    asm("mov.b64 %0, {%1, %1};" : "=l"(r) : "f"(w));
    return r;
}
__device__ __forceinline__ float2 unpk(u64 v) {
    float2 f;
    asm("mov.b64 {%0, %1}, %2;" : "=f"(f.x), "=f"(f.y) : "l"(v));
    return f;
}

// ---------------------------------------------------------------------------
__global__ void kinit(float* __restrict__ out) {
    int i = blockIdx.x * blockDim.x + threadIdx.x;
    if (i < 49152) out[OFF_XG + i] = 0.0f;
    if (i < 192)   out[OFF_POSG + i] = 0.0f;
    if (i < 64)    out[OFF_BATCHG + i] = (float)i;
    if (i < 8192)  out[OFF_BATCH2 + i] = (float)(i >> 7);
}

// ---------------------------------------------------------------------------
__global__ void knorm(const float* __restrict__ pos, float* __restrict__ out) {
    __shared__ float sbuf[256];
    __shared__ float smn[3], smx[3];
    __shared__ float sdiff;
    int tid = threadIdx.x, p = blockIdx.x;
    const float* base = pos + (size_t)p * NN * 3;

    float mn[3] = { FLT_MAX,  FLT_MAX,  FLT_MAX};
    float mx[3] = {-FLT_MAX, -FLT_MAX, -FLT_MAX};
    for (int i = tid; i < NN; i += 256) {
        float a = base[i * 3 + 0], b = base[i * 3 + 1], c = base[i * 3 + 2];
        mn[0] = fminf(mn[0], a); mx[0] = fmaxf(mx[0], a);
        mn[1] = fminf(mn[1], b); mx[1] = fmaxf(mx[1], b);
        mn[2] = fminf(mn[2], c); mx[2] = fmaxf(mx[2], c);
    }
    for (int r = 0; r < 6; r++) {
        sbuf[tid] = (r < 3) ? mn[r] : mx[r - 3];
        __syncthreads();
        for (int s = 128; s > 0; s >>= 1) {
            if (tid < s) {
                sbuf[tid] = (r < 3) ? fminf(sbuf[tid], sbuf[tid + s])
                                    : fmaxf(sbuf[tid], sbuf[tid + s]);
            }
            __syncthreads();
        }
        if (tid == 0) { if (r < 3) smn[r] = sbuf[0]; else smx[r - 3] = sbuf[0]; }
        __syncthreads();
    }
    if (tid == 0) {
        float d = fmaxf(fmaxf(smx[0] - smn[0], smx[1] - smn[1]), smx[2] - smn[2]);
        sdiff = d;
        out[OFF_VMIN + p * 3 + 0] = smn[0];
        out[OFF_VMIN + p * 3 + 1] = smn[1];
        out[OFF_VMIN + p * 3 + 2] = smn[2];
        out[OFF_DIFF + p] = d;
    }
    __syncthreads();
    float dv = sdiff;
    for (int o = tid; o < NN * 3; o += 256) {
        int d = o % 3;
        g_pn[(size_t)p * NN * 3 + o] = __fdiv_rn(base[o] - smn[d], dv);
    }
}

// ---------------------------------------------------------------------------
// FPS: fused update+argmax, 1 syncthreads/iter; warp argmax via 2x REDUX.
// ---------------------------------------------------------------------------
template <int NSRC, int M, int STAGE>
__global__ __launch_bounds__(256) void kfps() {
    const float* pts = (STAGE == 1) ? g_pn : g_q1;
    float* qout      = (STAGE == 1) ? g_q1 : g_q2;
    const int PT = NSRC / 256;

    __shared__ float sx[NSRC], sy[NSRC], sz[NSRC];
    __shared__ u64 wred[2][8];
    int tid = threadIdx.x, p = blockIdx.x;
    int lane = tid & 31, wid = tid >> 5;
    const float* base = pts + (size_t)p * NSRC * 3;

    float px[PT], py[PT], pz[PT], dd[PT];
    #pragma unroll
    for (int t = 0; t < PT; t++) {
        int i = tid + t * 256;
        float a = base[i * 3 + 0], b = base[i * 3 + 1], c = base[i * 3 + 2];
        sx[i] = a; sy[i] = b; sz[i] = c;
        px[t] = a; py[t] = b; pz[t] = c;
        dd[t] = FLT_MAX;
    }
    __syncthreads();
    float cx = sx[0], cy = sy[0], cz = sz[0];
    if (tid == 0) {
        qout[(size_t)p * M * 3 + 0] = cx;
        qout[(size_t)p * M * 3 + 1] = cy;
        qout[(size_t)p * M * 3 + 2] = cz;
    }

    for (int it = 1; it < M; it++) {
        unsigned bb = 0, binv = 0;   // d2 bits, ~idx
        #pragma unroll
        for (int t = 0; t < PT; t++) {
            float nd = d2_exact(px[t], py[t], pz[t], cx, cy, cz);
            dd[t] = fminf(dd[t], nd);
            unsigned db = __float_as_uint(dd[t]);
            if (db > bb) { bb = db; binv = ~(unsigned)(tid + t * 256); }
        }
        unsigned gmax = __reduce_max_sync(0xffffffffu, bb);
        unsigned cand = (bb == gmax) ? binv : 0u;
        unsigned ginv = __reduce_max_sync(0xffffffffu, cand);
        if (lane == 0) wred[it & 1][wid] = ((u64)gmax << 32) | (u64)ginv;
        __syncthreads();
        u64 m = wred[it & 1][0];
        #pragma unroll
        for (int w = 1; w < 8; w++) {
            u64 o = wred[it & 1][w];
            m = (o > m) ? o : m;
        }
        unsigned j = ~(unsigned)(m & 0xFFFFFFFFu);
        cx = sx[j]; cy = sy[j]; cz = sz[j];
        if (tid == 0) {
            qout[((size_t)p * M + it) * 3 + 0] = cx;
            qout[((size_t)p * M + it) * 3 + 1] = cy;
            qout[((size_t)p * M + it) * 3 + 2] = cz;
        }
    }
}

// ---------------------------------------------------------------------------
// Radius neighbors: ballot-compaction + REDUX argmin selection.
// ---------------------------------------------------------------------------
template <int NSRC, int M, int STAGE, int CAP>
__global__ __launch_bounds__(256) void kneigh() {
    const float* src  = (STAGE == 1) ? g_pn : g_q1;
    const float* qsrc = (STAGE == 1) ? g_q1 : g_q2;
    int* nidx         = (STAGE == 1) ? g_nidx1 : g_nidx2;
    const float r2    = (STAGE == 1) ? (float)(0.15 * 0.15) : (float)(0.3 * 0.3);

    extern __shared__ __align__(16) char dynbuf[];
    float4* spts = (float4*)dynbuf;                         // [NSRC]
    unsigned short* cand = (unsigned short*)(spts + NSRC);  // [8][CAP]

    int tid = threadIdx.x;
    int lane = tid & 31, w = tid >> 5;
    int tilesPerPatch = M / 16;
    int p    = blockIdx.x / tilesPerPatch;
    int tile = blockIdx.x % tilesPerPatch;
    const float* base = src + (size_t)p * NSRC * 3;

    for (int i = tid; i < NSRC; i += 256) {
        spts[i] = make_float4(base[i * 3 + 0], base[i * 3 + 1], base[i * 3 + 2], 0.0f);
    }
    __syncthreads();

    unsigned short* mycand = cand + (size_t)w * CAP;
    unsigned lmask = (1u << lane) - 1u;

    for (int g = 0; g < 2; g++) {
        int center = p * M + tile * 16 + g * 8 + w;
        float qx = qsrc[center * 3 + 0];
        float qy = qsrc[center * 3 + 1];
        float qz = qsrc[center * 3 + 2];

        int cnt = 0;
        for (int i = lane; i < NSRC; i += 32) {
            float4 pt = spts[i];
            float d2 = d2_exact(pt.x, pt.y, pt.z, qx, qy, qz);
            bool in = (d2 <= r2);
            unsigned mk = __ballot_sync(0xffffffffu, in);
            if (in) {
                int pos = cnt + __popc(mk & lmask);
                if (pos < CAP) mycand[pos] = (unsigned short)i;
            }
            cnt += __popc(mk);
        }

        if (cnt <= 32) {
            int v = (lane < cnt) ? (int)mycand[lane] : -1;
            nidx[center * KNB + lane] = v;
        } else if (cnt <= CAP) {
            unsigned last_d2 = 0, last_idx = 0;
            for (int k = 0; k < KNB; k++) {
                unsigned bd2 = 0xFFFFFFFFu, bidx = 0xFFFFFFFFu;
                for (int i = lane; i < cnt; i += 32) {
                    unsigned idx = mycand[i];
                    float4 pt = spts[idx];
                    float d2 = d2_exact(pt.x, pt.y, pt.z, qx, qy, qz);
                    unsigned db = __float_as_uint(d2);
                    bool ok = (k == 0) || (db > last_d2) ||
                              (db == last_d2 && idx > last_idx);
                    if (ok && db < bd2) { bd2 = db; bidx = idx; }
                }
                unsigned gmin = __reduce_min_sync(0xffffffffu, bd2);
                unsigned cd = (bd2 == gmin) ? bidx : 0xFFFFFFFFu;
                unsigned gidx = __reduce_min_sync(0xffffffffu, cd);
                if (lane == 0) nidx[center * KNB + k] = (int)gidx;
                last_d2 = gmin; last_idx = gidx;
            }
        } else {
            unsigned last_d2 = 0, last_idx = 0;
            for (int k = 0; k < KNB; k++) {
                unsigned bd2 = 0xFFFFFFFFu, bidx = 0xFFFFFFFFu;
                for (int i = lane; i < NSRC; i += 32) {
                    float4 pt = spts[i];
                    float d2 = d2_exact(pt.x, pt.y, pt.z, qx, qy, qz);
                    if (d2 <= r2) {
                        unsigned db = __float_as_uint(d2);
                        unsigned idx = (unsigned)i;
                        bool ok = (k == 0) || (db > last_d2) ||
                                  (db == last_d2 && idx > last_idx);
                        if (ok && db < bd2) { bd2 = db; bidx = idx; }
                    }
                }
                unsigned gmin = __reduce_min_sync(0xffffffffu, bd2);
                unsigned cd = (bd2 == gmin) ? bidx : 0xFFFFFFFFu;
                unsigned gidx = __reduce_min_sync(0xffffffffu, cd);
                if (lane == 0) nidx[center * KNB + k] = (int)gidx;
                last_d2 = gmin; last_idx = gidx;
            }
        }
    }
}

// ---------------------------------------------------------------------------
// Stage-1 MLP: feat[32,6] -> 64 -> 128, max over valid K.
// 2 groups of 128 threads; 8 centers/block.
// Layer 1: 2ch x 8k register-blocked, weights via __ldg (transient regs).
// Layer 2: 4ch x 8k register-blocked, weights staged in shared (round-8).
// ---------------------------------------------------------------------------
__global__ __launch_bounds__(256) void kmlp1(
    const float* __restrict__ W1a, const float* __restrict__ b1a,
    const float* __restrict__ W1b, const float* __restrict__ b1b) {
    extern __shared__ __align__(16) float sm1[];
    float* sWb = sm1;                  // 64*128
    float* sbb = sWb + 64 * 128;       // 128
    float* sfeatA = sbb + 128;         // [2][6*32]
    float* sh1A   = sfeatA + 2 * 6 * 32;  // [2][64*32]
    __shared__ int   sj[2][32];
    __shared__ float sq[2][3];

    int tid = threadIdx.x;
    int grp = tid >> 7, t = tid & 127;
    float* sfeat = sfeatA + grp * 6 * 32;
    float* sh1   = sh1A + grp * 64 * 32;

    for (int i = tid; i < 64 * 128; i += 256) sWb[i] = W1b[i];
    if (tid < 128) sbb[tid] = b1b[tid];

    int kg = t & 3, k0 = kg * 8;
    int c0 = (t >> 2) * 4;             // layer-2 channels (4)
    int c1 = (t >> 2) * 2;             // layer-1 channels (2): 0..62

    for (int cc = 0; cc < 4; cc++) {
        __syncthreads();
        int center = blockIdx.x * 8 + cc * 2 + grp;
        int p = center >> 9;
        if (t < 32) sj[grp][t] = g_nidx1[center * KNB + t];
        if (t < 3)  sq[grp][t] = g_q1[center * 3 + t];
        __syncthreads();

        for (int o = t; o < 192; o += 128) {
            int k = o & 31, f = o >> 5;
            int j = sj[grp][k];
            float v = 0.0f;
            if (j >= 0) {
                int d = (f < 3) ? f : (f - 3);
                float pj = g_pn[((size_t)p * NN + j) * 3 + d];
                v = (f < 3) ? pj : (pj - sq[grp][d]);
            }
            sfeat[f * 32 + k] = v;
        }
        __syncthreads();

        // ---- layer 1: 6 -> 64, 2ch x 8k (f32x2) ----
        {
            float2 bv = __ldg((const float2*)&b1a[c1]);
            u64 a0 = dup2(bv.x), bseed1 = dup2(bv.y);
            u64 a[8];
            a[0] = a0; a[1] = a0; a[2] = a0; a[3] = a0;
            a[4] = bseed1; a[5] = bseed1; a[6] = bseed1; a[7] = bseed1;
            #pragma unroll
            for (int f = 0; f < 6; f++) {
                float2 w2 = __ldg((const float2*)&W1a[f * 64 + c1]);
                const ulonglong2* hp = (const ulonglong2*)&sfeat[f * 32 + k0];
                ulonglong2 ha = hp[0], hb = hp[1];
                u64 w0 = dup2(w2.x), w1 = dup2(w2.y);
                a[0] = fma2(ha.x, w0, a[0]); a[1] = fma2(ha.y, w0, a[1]);
                a[2] = fma2(hb.x, w0, a[2]); a[3] = fma2(hb.y, w0, a[3]);
                a[4] = fma2(ha.x, w1, a[4]); a[5] = fma2(ha.y, w1, a[5]);
                a[6] = fma2(hb.x, w1, a[6]); a[7] = fma2(hb.y, w1, a[7]);
            }
            #pragma unroll
            for (int ci = 0; ci < 2; ci++) {
                float2 f0 = unpk(a[ci * 4 + 0]);
                float2 f1 = unpk(a[ci * 4 + 1]);
                float2 f2 = unpk(a[ci * 4 + 2]);
                float2 f3 = unpk(a[ci * 4 + 3]);
                float4 lo, hi;
                lo.x = fmaxf(f0.x, 0.0f); lo.y = fmaxf(f0.y, 0.0f);
                lo.z = fmaxf(f1.x, 0.0f); lo.w = fmaxf(f1.y, 0.0f);
                hi.x = fmaxf(f2.x, 0.0f); hi.y = fmaxf(f2.y, 0.0f);
                hi.z = fmaxf(f3.x, 0.0f); hi.w = fmaxf(f3.y, 0.0f);
                *(float4*)&sh1[(c1 + ci) * 32 + k0]     = lo;
                *(float4*)&sh1[(c1 + ci) * 32 + k0 + 4] = hi;
            }
        }
        __syncthreads();

        // ---- layer 2: 64 -> 128, 4ch x 8k (round-8) ----
        {
            u64 acc[16];
            #pragma unroll
            for (int q = 0; q < 16; q++) acc[q] = 0ull;
            #pragma unroll 4
            for (int i = 0; i < 64; i++) {
                float4 w4 = *(const float4*)&sWb[i * 128 + c0];
                const ulonglong2* hp = (const ulonglong2*)&sh1[i * 32 + k0];
                ulonglong2 ha = hp[0], hb = hp[1];
                u64 w0 = dup2(w4.x), w1 = dup2(w4.y), w2 = dup2(w4.z), w3 = dup2(w4.w);
                acc[0]  = fma2(ha.x, w0, acc[0]);  acc[1]  = fma2(ha.y, w0, acc[1]);
                acc[2]  = fma2(hb.x, w0, acc[2]);  acc[3]  = fma2(hb.y, w0, acc[3]);
                acc[4]  = fma2(ha.x, w1, acc[4]);  acc[5]  = fma2(ha.y, w1, acc[5]);
                acc[6]  = fma2(hb.x, w1, acc[6]);  acc[7]  = fma2(hb.y, w1, acc[7]);
                acc[8]  = fma2(ha.x, w2, acc[8]);  acc[9]  = fma2(ha.y, w2, acc[9]);
                acc[10] = fma2(hb.x, w2, acc[10]); acc[11] = fma2(hb.y, w2, acc[11]);
                acc[12] = fma2(ha.x, w3, acc[12]); acc[13] = fma2(ha.y, w3, acc[13]);
                acc[14] = fma2(hb.x, w3, acc[14]); acc[15] = fma2(hb.y, w3, acc[15]);
            }
            float4 b4 = *(const float4*)&sbb[c0];
            float bias[4] = {b4.x, b4.y, b4.z, b4.w};
            #pragma unroll
            for (int ci = 0; ci < 4; ci++) {
                float b = bias[ci];
                float m = -FLT_MAX;
                #pragma unroll
                for (int qq = 0; qq < 4; qq++) {
                    float2 f = unpk(acc[ci * 4 + qq]);
                    if (sj[grp][k0 + 2 * qq + 0] >= 0) m = fmaxf(m, fmaxf(f.x + b, 0.0f));
                    if (sj[grp][k0 + 2 * qq + 1] >= 0) m = fmaxf(m, fmaxf(f.y + b, 0.0f));
                }
                m = fmaxf(m, __shfl_xor_sync(0xffffffffu, m, 1));
                m = fmaxf(m, __shfl_xor_sync(0xffffffffu, m, 2));
                if (kg == 0) g_x1[(size_t)center * 128 + c0 + ci] = m;
            }
        }
    }
}

// ---------------------------------------------------------------------------
// Stage-2 MLP: feat[32,131] -> 256 -> 384, max over valid K.
// One center per 256-thread block. Register-blocked 4c x 8k per thread.
// (round-8 version)
// ---------------------------------------------------------------------------
__global__ __launch_bounds__(256) void kmlp2(
    const float* __restrict__ W2a, const float* __restrict__ b2a,
    const float* __restrict__ W2b, const float* __restrict__ b2b,
    float* __restrict__ out) {
    extern __shared__ __align__(16) float smem2[];
    float* sfeat = smem2;              // [131][32]
    float* sh1   = sfeat + 131 * 32;   // [256][32]
    __shared__ int   sj[32];
    __shared__ float sq[3];
    int t = threadIdx.x;
    int center = blockIdx.x;
    int p = center >> 7;
    if (t < 32) sj[t] = g_nidx2[center * KNB + t];
    if (t < 3) {
        float qv = g_q2[center * 3 + t];
        sq[t] = qv;
        out[OFF_Q2 + center * 3 + t] = qv;
    }
    __syncthreads();

    for (int o = t; o < 131 * 32; o += 256) {
        int k = o & 31, i = o >> 5;
        int j = sj[k];
        float v = 0.0f;
        if (j >= 0) {
            if (i < 128) v = g_x1[((size_t)p * M1 + j) * 128 + i];
            else         v = g_q1[((size_t)p * M1 + j) * 3 + (i - 128)] - sq[i - 128];
        }
        sfeat[i * 32 + k] = v;
    }
    __syncthreads();

    int kg = t & 3, k0 = kg * 8;
    int c0 = (t >> 2) * 4;             // 0..252

    // ---- layer A: 131 -> 256 ----
    {
        u64 acc[16];
        #pragma unroll
        for (int q = 0; q < 16; q++) acc[q] = 0ull;
        #pragma unroll 4
        for (int i = 0; i < 131; i++) {
            float4 w4 = __ldg((const float4*)&W2a[i * 256 + c0]);
            const ulonglong2* hp = (const ulonglong2*)&sfeat[i * 32 + k0];
            ulonglong2 ha = hp[0], hb = hp[1];
            u64 w0 = dup2(w4.x), w1 = dup2(w4.y), w2 = dup2(w4.z), w3 = dup2(w4.w);
            acc[0]  = fma2(ha.x, w0, acc[0]);  acc[1]  = fma2(ha.y, w0, acc[1]);
            acc[2]  = fma2(hb.x, w0, acc[2]);  acc[3]  = fma2(hb.y, w0, acc[3]);
            acc[4]  = fma2(ha.x, w1, acc[4]);  acc[5]  = fma2(ha.y, w1, acc[5]);
            acc[6]  = fma2(hb.x, w1, acc[6]);  acc[7]  = fma2(hb.y, w1, acc[7]);
            acc[8]  = fma2(ha.x, w2, acc[8]);  acc[9]  = fma2(ha.y, w2, acc[9]);
            acc[10] = fma2(hb.x, w2, acc[10]); acc[11] = fma2(hb.y, w2, acc[11]);
            acc[12] = fma2(ha.x, w3, acc[12]); acc[13] = fma2(ha.y, w3, acc[13]);
            acc[14] = fma2(hb.x, w3, acc[14]); acc[15] = fma2(hb.y, w3, acc[15]);
        }
        float4 b4 = __ldg((const float4*)&b2a[c0]);
        float bias[4] = {b4.x, b4.y, b4.z, b4.w};
        #pragma unroll
        for (int ci = 0; ci < 4; ci++) {
            float b = bias[ci];
            float2 f0 = unpk(acc[ci * 4 + 0]);
            float2 f1 = unpk(acc[ci * 4 + 1]);
            float2 f2 = unpk(acc[ci * 4 + 2]);
            float2 f3 = unpk(acc[ci * 4 + 3]);
            float4 lo, hi;
            lo.x = fmaxf(f0.x + b, 0.0f); lo.y = fmaxf(f0.y + b, 0.0f);
            lo.z = fmaxf(f1.x + b, 0.0f); lo.w = fmaxf(f1.y + b, 0.0f);
            hi.x = fmaxf(f2.x + b, 0.0f); hi.y = fmaxf(f2.y + b, 0.0f);
            hi.z = fmaxf(f3.x + b, 0.0f); hi.w = fmaxf(f3.y + b, 0.0f);
            *(float4*)&sh1[(c0 + ci) * 32 + k0] = lo;
            *(float4*)&sh1[(c0 + ci) * 32 + k0 + 4] = hi;
        }
    }
    __syncthreads();

    // ---- layer B: 256 -> 384 (2 passes; second pass half-active) ----
    #pragma unroll
    for (int pass = 0; pass < 2; pass++) {
        int cb = pass * 256 + c0;
        if (cb < 384) {
            u64 acc[16];
            #pragma unroll
            for (int q = 0; q < 16; q++) acc[q] = 0ull;
            #pragma unroll 4
            for (int i = 0; i < 256; i++) {
                float4 w4 = __ldg((const float4*)&W2b[i * 384 + cb]);
                const ulonglong2* hp = (const ulonglong2*)&sh1[i * 32 + k0];
                ulonglong2 ha = hp[0], hb = hp[1];
                u64 w0 = dup2(w4.x), w1 = dup2(w4.y), w2 = dup2(w4.z), w3 = dup2(w4.w);
                acc[0]  = fma2(ha.x, w0, acc[0]);  acc[1]  = fma2(ha.y, w0, acc[1]);
                acc[2]  = fma2(hb.x, w0, acc[2]);  acc[3]  = fma2(hb.y, w0, acc[3]);
                acc[4]  = fma2(ha.x, w1, acc[4]);  acc[5]  = fma2(ha.y, w1, acc[5]);
                acc[6]  = fma2(hb.x, w1, acc[6]);  acc[7]  = fma2(hb.y, w1, acc[7]);
                acc[8]  = fma2(ha.x, w2, acc[8]);  acc[9]  = fma2(ha.y, w2, acc[9]);
                acc[10] = fma2(hb.x, w2, acc[10]); acc[11] = fma2(hb.y, w2, acc[11]);
                acc[12] = fma2(ha.x, w3, acc[12]); acc[13] = fma2(ha.y, w3, acc[13]);
                acc[14] = fma2(hb.x, w3, acc[14]); acc[15] = fma2(hb.y, w3, acc[15]);
            }
            float4 b4 = __ldg((const float4*)&b2b[cb]);
            float bias[4] = {b4.x, b4.y, b4.z, b4.w};
            #pragma unroll
            for (int ci = 0; ci < 4; ci++) {
                float b = bias[ci];
                float m = -FLT_MAX;
                #pragma unroll
                for (int qq = 0; qq < 4; qq++) {
                    float2 f = unpk(acc[ci * 4 + qq]);
                    if (sj[k0 + 2 * qq + 0] >= 0) m = fmaxf(m, fmaxf(f.x + b, 0.0f));
                    if (sj[k0 + 2 * qq + 1] >= 0) m = fmaxf(m, fmaxf(f.y + b, 0.0f));
                }
                m = fmaxf(m, __shfl_xor_sync(0xffffffffu, m, 1));
                m = fmaxf(m, __shfl_xor_sync(0xffffffffu, m, 2));
                if (kg == 0) out[OFF_X2 + (size_t)center * 384 + cb + ci] = m;
            }
        }
    }
}

// ---------------------------------------------------------------------------
// Stage-3 MLP: feat[387] -> 512 -> 768; 16 centers/block, 256 threads.
// Register-blocked 4 channels x 4 centers per thread. (round-8 version)
// ---------------------------------------------------------------------------
__global__ __launch_bounds__(256) void kmlp3(
    const float* __restrict__ W3a, const float* __restrict__ b3a,
    const float* __restrict__ W3b, const float* __restrict__ b3b,
    float* __restrict__ out) {
    extern __shared__ __align__(16) char smem3[];
    float* sfeat = (float*)smem3;          // [387][16]
    float* sh1   = sfeat + 387 * 16;       // [512][16]
    int t = threadIdx.x;
    int base = blockIdx.x * 16;
    int p = base >> 7;

    for (int o = t; o < 387 * 16; o += 256) {
        int cen = o & 15, i = o >> 4;
        int center = base + cen;
        float v = (i < 384) ? out[OFF_X2 + (size_t)center * 384 + i]
                            : out[OFF_Q2 + center * 3 + (i - 384)];
        sfeat[i * 16 + cen] = v;
    }
    __syncthreads();

    int eg = t & 3, e0 = eg * 4;
    int c0 = (t >> 2) * 4;                  // 0..252

    // ---- layer A: 387 -> 512 (2 passes) ----
    #pragma unroll
    for (int pass = 0; pass < 2; pass++) {
        int ca = pass * 256 + c0;           // < 512
        u64 acc[8];
        #pragma unroll
        for (int q = 0; q < 8; q++) acc[q] = 0ull;
        #pragma unroll 4
        for (int i = 0; i < 387; i++) {
            float4 w4 = __ldg((const float4*)&W3a[i * 512 + ca]);
            ulonglong2 h = *(const ulonglong2*)&sfeat[i * 16 + e0];
            u64 w0 = dup2(w4.x), w1 = dup2(w4.y), w2 = dup2(w4.z), w3 = dup2(w4.w);
            acc[0] = fma2(h.x, w0, acc[0]); acc[1] = fma2(h.y, w0, acc[1]);
            acc[2] = fma2(h.x, w1, acc[2]); acc[3] = fma2(h.y, w1, acc[3]);
            acc[4] = fma2(h.x, w2, acc[4]); acc[5] = fma2(h.y, w2, acc[5]);
            acc[6] = fma2(h.x, w3, acc[6]); acc[7] = fma2(h.y, w3, acc[7]);
        }
        float4 b4 = __ldg((const float4*)&b3a[ca]);
        float bias[4] = {b4.x, b4.y, b4.z, b4.w};
        #pragma unroll
        for (int ci = 0; ci < 4; ci++) {
            float b = bias[ci];
            float2 f0 = unpk(acc[ci * 2 + 0]);
            float2 f1 = unpk(acc[ci * 2 + 1]);
            float4 s;
            s.x = fmaxf(f0.x + b, 0.0f); s.y = fmaxf(f0.y + b, 0.0f);
            s.z = fmaxf(f1.x + b, 0.0f); s.w = fmaxf(f1.y + b, 0.0f);
            *(float4*)&sh1[(ca + ci) * 16 + e0] = s;
        }
    }
    __syncthreads();

    // ---- layer B: 512 -> 768 (3 passes) + global max ----
    #pragma unroll
    for (int pass = 0; pass < 3; pass++) {
        int cb = pass * 256 + c0;           // < 768
        u64 acc[8];
        #pragma unroll
        for (int q = 0; q < 8; q++) acc[q] = 0ull;
        #pragma unroll 4
        for (int i = 0; i < 512; i++) {
            float4 w4 = __ldg((const float4*)&W3b[i * 768 + cb]);
            ulonglong2 h = *(const ulonglong2*)&sh1[i * 16 + e0];
            u64 w0 = dup2(w4.x), w1 = dup2(w4.y), w2 = dup2(w4.z), w3 = dup2(w4.w);
            acc[0] = fma2(h.x, w0, acc[0]); acc[1] = fma2(h.y, w0, acc[1]);
            acc[2] = fma2(h.x, w1, acc[2]); acc[3] = fma2(h.y, w1, acc[3]);
            acc[4] = fma2(h.x, w2, acc[4]); acc[5] = fma2(h.y, w2, acc[5]);
            acc[6] = fma2(h.x, w3, acc[6]); acc[7] = fma2(h.y, w3, acc[7]);
        }
        float4 b4 = __ldg((const float4*)&b3b[cb]);
        float bias[4] = {b4.x, b4.y, b4.z, b4.w};
        #pragma unroll
        for (int ci = 0; ci < 4; ci++) {
            float b = bias[ci];
            float2 f0 = unpk(acc[ci * 2 + 0]);
            float2 f1 = unpk(acc[ci * 2 + 1]);
            float m = fmaxf(fmaxf(f0.x + b, 0.0f), fmaxf(f0.y + b, 0.0f));
            m = fmaxf(m, fmaxf(f1.x + b, 0.0f));
            m = fmaxf(m, fmaxf(f1.y + b, 0.0f));
            m = fmaxf(m, __shfl_xor_sync(0xffffffffu, m, 1));
            m = fmaxf(m, __shfl_xor_sync(0xffffffffu, m, 2));
            if (eg == 0)
                atomicMax((int*)&out[OFF_XG + p * 768 + cb + ci], __float_as_int(m));
        }
    }
}

// ---------------------------------------------------------------------------
extern "C" void kernel_launch(void* const* d_in, const int* in_sizes, int n_in,
                              void* d_out, int out_size) {
    const float* pos = (const float*)d_in[0];
    const float* W1a = (const float*)d_in[2];
    const float* b1a = (const float*)d_in[3];
    const float* W1b = (const float*)d_in[4];
    const float* b1b = (const float*)d_in[5];
    const float* W2a = (const float*)d_in[6];
    const float* b2a = (const float*)d_in[7];
    const float* W2b = (const float*)d_in[8];
    const float* b2b = (const float*)d_in[9];
    const float* W3a = (const float*)d_in[10];
    const float* b3a = (const float*)d_in[11];
    const float* W3b = (const float*)d_in[12];
    const float* b3b = (const float*)d_in[13];
    float* out = (float*)d_out;

    const int CAP1 = 1024, CAP2 = 512;
    const int NEIGH1_SMEM = NN * 16 + 8 * CAP1 * 2;      // 49152
    const int NEIGH2_SMEM = M1 * 16 + 8 * CAP2 * 2;      // 16384
    const int MLP1_SMEM   = (64 * 128 + 128 + 2 * (6 * 32 + 64 * 32)) * 4;  // 51200
    const int MLP2_SMEM   = (131 * 32 + 256 * 32) * 4;   // 49536
    const int MLP3_SMEM   = (387 * 16 + 512 * 16) * 4;   // 57536
    cudaFuncSetAttribute(kneigh<NN, M1, 1, CAP1>,
                         cudaFuncAttributeMaxDynamicSharedMemorySize, NEIGH1_SMEM);
    cudaFuncSetAttribute(kneigh<M1, M2, 2, CAP2>,
                         cudaFuncAttributeMaxDynamicSharedMemorySize, NEIGH2_SMEM);
    cudaFuncSetAttribute(kmlp1,
                         cudaFuncAttributeMaxDynamicSharedMemorySize, MLP1_SMEM);
    cudaFuncSetAttribute(kmlp2,
                         cudaFuncAttributeMaxDynamicSharedMemorySize, MLP2_SMEM);
    cudaFuncSetAttribute(kmlp3,
                         cudaFuncAttributeMaxDynamicSharedMemorySize, MLP3_SMEM);

    // Launch order: index 3 (kmlp1) is the ncu-profiled launch.
    knorm<<<PP, 256>>>(pos, out);                                        // 0
    kfps<NN, M1, 1><<<PP, 256>>>();                                      // 1
    kneigh<NN, M1, 1, CAP1><<<PP * M1 / 16, 256, NEIGH1_SMEM>>>();       // 2
    kmlp1<<<PP * M1 / 8, 256, MLP1_SMEM>>>(W1a, b1a, W1b, b1b);          // 3 <- profiled
    kfps<M1, M2, 2><<<PP, 256>>>();                                      // 4
    kneigh<M1, M2, 2, CAP2><<<PP * M2 / 16, 256, NEIGH2_SMEM>>>();       // 5
    kmlp2<<<PP * M2, 256, MLP2_SMEM>>>(W2a, b2a, W2b, b2b, out);         // 6
    kinit<<<192, 256>>>(out);                                            // 7
    kmlp3<<<PP * M2 / 16, 256, MLP3_SMEM>>>(W3a, b3a, W3b, b3b, out);    // 8
}

// round 11
// speedup vs baseline: 1.1195x; 1.0893x over previous
#include <cuda_runtime.h>
#include <cuda_bf16.h>
#include <float.h>

#define PP  64
#define NN  2048
#define M1  512
#define M2  128
#define KNB 32

typedef unsigned long long u64;

// ---- output layout (float32, concatenated in reference return order) ----
#define OFF_XG     0            // [64,768]
#define OFF_POSG   49152        // [64,3]
#define OFF_BATCHG 49344        // [64]
#define OFF_X2     49408        // [8192,384]
#define OFF_Q2     3195136      // [8192,3]
#define OFF_BATCH2 3219712      // [8192]
#define OFF_VMIN   3227904      // [64,3]
#define OFF_DIFF   3228096      // [64]

// ---- scratch (device globals; no allocation allowed) ----
__device__ float g_pn[PP * NN * 3];
__device__ float g_q1[PP * M1 * 3];
__device__ float g_q2[PP * M2 * 3];
__device__ int   g_nidx1[PP * M1 * KNB];
__device__ int   g_nidx2[PP * M2 * KNB];
__device__ float g_x1[PP * M1 * 128];
__device__ float g_ypn[PP * NN * 64];    // pn @ (W1a[0:3]+W1a[3:6]) + b1a
__device__ float g_yz[PP * M1 * 256];    // [x1;q1] @ W2a + b2a

// Exact (non-contracted) squared distance, (dx^2 + dy^2) + dz^2 order.
__device__ __forceinline__ float d2_exact(float ax, float ay, float az,
                                          float bx, float by, float bz) {
    float dx = ax - bx, dy = ay - by, dz = az - bz;
    float s = __fmul_rn(dx, dx);
    s = __fadd_rn(s, __fmul_rn(dy, dy));
    s = __fadd_rn(s, __fmul_rn(dz, dz));
    return s;
}

// ---- packed f32x2 helpers (Blackwell FFMA2) ----
__device__ __forceinline__ u64 fma2(u64 a, u64 b, u64 c) {
    u64 d;
    asm("fma.rn.f32x2 %0, %1, %2, %3;" : "=l"(d) : "l"(a), "l"(b), "l"(c));
    return d;
}
__device__ __forceinline__ u64 dup2(float w) {
    u64 r;
    asm("mov.b64 %0, {%1, %1};" : "=l"(r) : "f"(w));
    return r;
}
__device__ __forceinline__ float2 unpk(u64 v) {
    float2 f;
    asm("mov.b64 {%0, %1}, %2;" : "=f"(f.x), "=f"(f.y) : "l"(v));
    return f;
}

// ---------------------------------------------------------------------------
__global__ void kinit(float* __restrict__ out) {
    int i = blockIdx.x * blockDim.x + threadIdx.x;
    if (i < 49152) out[OFF_XG + i] = 0.0f;
    if (i < 192)   out[OFF_POSG + i] = 0.0f;
    if (i < 64)    out[OFF_BATCHG + i] = (float)i;
    if (i < 8192)  out[OFF_BATCH2 + i] = (float)(i >> 7);
}

// ---------------------------------------------------------------------------
__global__ void knorm(const float* __restrict__ pos, float* __restrict__ out) {
    __shared__ float sbuf[256];
    __shared__ float smn[3], smx[3];
    __shared__ float sdiff;
    int tid = threadIdx.x, p = blockIdx.x;
    const float* base = pos + (size_t)p * NN * 3;

    float mn[3] = { FLT_MAX,  FLT_MAX,  FLT_MAX};
    float mx[3] = {-FLT_MAX, -FLT_MAX, -FLT_MAX};
    for (int i = tid; i < NN; i += 256) {
        float a = base[i * 3 + 0], b = base[i * 3 + 1], c = base[i * 3 + 2];
        mn[0] = fminf(mn[0], a); mx[0] = fmaxf(mx[0], a);
        mn[1] = fminf(mn[1], b); mx[1] = fmaxf(mx[1], b);
        mn[2] = fminf(mn[2], c); mx[2] = fmaxf(mx[2], c);
    }
    for (int r = 0; r < 6; r++) {
        sbuf[tid] = (r < 3) ? mn[r] : mx[r - 3];
        __syncthreads();
        for (int s = 128; s > 0; s >>= 1) {
            if (tid < s) {
                sbuf[tid] = (r < 3) ? fminf(sbuf[tid], sbuf[tid + s])
                                    : fmaxf(sbuf[tid], sbuf[tid + s]);
            }
            __syncthreads();
        }
        if (tid == 0) { if (r < 3) smn[r] = sbuf[0]; else smx[r - 3] = sbuf[0]; }
        __syncthreads();
    }
    if (tid == 0) {
        float d = fmaxf(fmaxf(smx[0] - smn[0], smx[1] - smn[1]), smx[2] - smn[2]);
        sdiff = d;
        out[OFF_VMIN + p * 3 + 0] = smn[0];
        out[OFF_VMIN + p * 3 + 1] = smn[1];
        out[OFF_VMIN + p * 3 + 2] = smn[2];
        out[OFF_DIFF + p] = d;
    }
    __syncthreads();
    float dv = sdiff;
    for (int o = tid; o < NN * 3; o += 256) {
        int d = o % 3;
        g_pn[(size_t)p * NN * 3 + o] = __fdiv_rn(base[o] - smn[d], dv);
    }
}

// ---------------------------------------------------------------------------
// Precompute 1: Ypn[pt][64] = pn_pt @ (W1a[0:3]+W1a[3:6]) + b1a
// One thread per (point, 4 channels).
// ---------------------------------------------------------------------------
__global__ __launch_bounds__(256) void kpre1(const float* __restrict__ W1a,
                                             const float* __restrict__ b1a) {
    int idx = blockIdx.x * 256 + threadIdx.x;   // PP*NN*16
    int pt = idx >> 4;
    int c  = (idx & 15) * 4;
    float x = g_pn[pt * 3 + 0];
    float y = g_pn[pt * 3 + 1];
    float z = g_pn[pt * 3 + 2];
    float4 acc = __ldg((const float4*)&b1a[c]);
    #pragma unroll
    for (int d = 0; d < 3; d++) {
        float4 wa = __ldg((const float4*)&W1a[d * 64 + c]);
        float4 wb = __ldg((const float4*)&W1a[(3 + d) * 64 + c]);
        float s = (d == 0) ? x : ((d == 1) ? y : z);
        acc.x += (wa.x + wb.x) * s;
        acc.y += (wa.y + wb.y) * s;
        acc.z += (wa.z + wb.z) * s;
        acc.w += (wa.w + wb.w) * s;
    }
    *(float4*)&g_ypn[(size_t)pt * 64 + c] = acc;
}

// ---------------------------------------------------------------------------
// Precompute 2: YZ[r][256] = [x1_r ; q1_r] @ W2a + b2a  (no relu, no center)
// 32 source rows per block, 256 threads, register-blocked 4ch x 8row.
// ---------------------------------------------------------------------------
__global__ __launch_bounds__(256) void kpre2(const float* __restrict__ W2a,
                                             const float* __restrict__ b2a) {
    extern __shared__ __align__(16) float sfp[];   // [131][32]
    int t = threadIdx.x;
    int jb = blockIdx.x * 32;                       // global source row base

    for (int o = t; o < 131 * 32; o += 256) {
        int k = o & 31, i = o >> 5;
        float v = (i < 128) ? g_x1[(size_t)(jb + k) * 128 + i]
                            : g_q1[(size_t)(jb + k) * 3 + (i - 128)];
        sfp[i * 32 + k] = v;
    }
    __syncthreads();

    int kg = t & 3, k0 = kg * 8;
    int c0 = (t >> 2) * 4;

    u64 acc[16];
    #pragma unroll
    for (int q = 0; q < 16; q++) acc[q] = 0ull;
    #pragma unroll 4
    for (int i = 0; i < 131; i++) {
        float4 w4 = __ldg((const float4*)&W2a[i * 256 + c0]);
        const ulonglong2* hp = (const ulonglong2*)&sfp[i * 32 + k0];
        ulonglong2 ha = hp[0], hb = hp[1];
        u64 w0 = dup2(w4.x), w1 = dup2(w4.y), w2 = dup2(w4.z), w3 = dup2(w4.w);
        acc[0]  = fma2(ha.x, w0, acc[0]);  acc[1]  = fma2(ha.y, w0, acc[1]);
        acc[2]  = fma2(hb.x, w0, acc[2]);  acc[3]  = fma2(hb.y, w0, acc[3]);
        acc[4]  = fma2(ha.x, w1, acc[4]);  acc[5]  = fma2(ha.y, w1, acc[5]);
        acc[6]  = fma2(hb.x, w1, acc[6]);  acc[7]  = fma2(hb.y, w1, acc[7]);
        acc[8]  = fma2(ha.x, w2, acc[8]);  acc[9]  = fma2(ha.y, w2, acc[9]);
        acc[10] = fma2(hb.x, w2, acc[10]); acc[11] = fma2(hb.y, w2, acc[11]);
        acc[12] = fma2(ha.x, w3, acc[12]); acc[13] = fma2(ha.y, w3, acc[13]);
        acc[14] = fma2(hb.x, w3, acc[14]); acc[15] = fma2(hb.y, w3, acc[15]);
    }
    float4 b4 = __ldg((const float4*)&b2a[c0]);
    #pragma unroll
    for (int kk = 0; kk < 8; kk++) {
        int q = kk >> 1;
        float2 f0 = unpk(acc[0 * 4 + q]);
        float2 f1 = unpk(acc[1 * 4 + q]);
        float2 f2 = unpk(acc[2 * 4 + q]);
        float2 f3 = unpk(acc[3 * 4 + q]);
        float4 o;
        if (kk & 1) { o.x = f0.y + b4.x; o.y = f1.y + b4.y; o.z = f2.y + b4.z; o.w = f3.y + b4.w; }
        else        { o.x = f0.x + b4.x; o.y = f1.x + b4.y; o.z = f2.x + b4.z; o.w = f3.x + b4.w; }
        *(float4*)&g_yz[(size_t)(jb + k0 + kk) * 256 + c0] = o;
    }
}

// ---------------------------------------------------------------------------
// FPS: fused update+argmax, 1 syncthreads/iter; warp argmax via 2x REDUX.
// ---------------------------------------------------------------------------
template <int NSRC, int M, int STAGE>
__global__ __launch_bounds__(256) void kfps() {
    const float* pts = (STAGE == 1) ? g_pn : g_q1;
    float* qout      = (STAGE == 1) ? g_q1 : g_q2;
    const int PT = NSRC / 256;

    __shared__ float sx[NSRC], sy[NSRC], sz[NSRC];
    __shared__ u64 wred[2][8];
    int tid = threadIdx.x, p = blockIdx.x;
    int lane = tid & 31, wid = tid >> 5;
    const float* base = pts + (size_t)p * NSRC * 3;

    float px[PT], py[PT], pz[PT], dd[PT];
    #pragma unroll
    for (int t = 0; t < PT; t++) {
        int i = tid + t * 256;
        float a = base[i * 3 + 0], b = base[i * 3 + 1], c = base[i * 3 + 2];
        sx[i] = a; sy[i] = b; sz[i] = c;
        px[t] = a; py[t] = b; pz[t] = c;
        dd[t] = FLT_MAX;
    }
    __syncthreads();
    float cx = sx[0], cy = sy[0], cz = sz[0];
    if (tid == 0) {
        qout[(size_t)p * M * 3 + 0] = cx;
        qout[(size_t)p * M * 3 + 1] = cy;
        qout[(size_t)p * M * 3 + 2] = cz;
    }

    for (int it = 1; it < M; it++) {
        unsigned bb = 0, binv = 0;   // d2 bits, ~idx
        #pragma unroll
        for (int t = 0; t < PT; t++) {
            float nd = d2_exact(px[t], py[t], pz[t], cx, cy, cz);
            dd[t] = fminf(dd[t], nd);
            unsigned db = __float_as_uint(dd[t]);
            if (db > bb) { bb = db; binv = ~(unsigned)(tid + t * 256); }
        }
        unsigned gmax = __reduce_max_sync(0xffffffffu, bb);
        unsigned cand = (bb == gmax) ? binv : 0u;
        unsigned ginv = __reduce_max_sync(0xffffffffu, cand);
        if (lane == 0) wred[it & 1][wid] = ((u64)gmax << 32) | (u64)ginv;
        __syncthreads();
        u64 m = wred[it & 1][0];
        #pragma unroll
        for (int w = 1; w < 8; w++) {
            u64 o = wred[it & 1][w];
            m = (o > m) ? o : m;
        }
        unsigned j = ~(unsigned)(m & 0xFFFFFFFFu);
        cx = sx[j]; cy = sy[j]; cz = sz[j];
        if (tid == 0) {
            qout[((size_t)p * M + it) * 3 + 0] = cx;
            qout[((size_t)p * M + it) * 3 + 1] = cy;
            qout[((size_t)p * M + it) * 3 + 2] = cz;
        }
    }
}

// ---------------------------------------------------------------------------
// Radius neighbors: ballot-compaction + REDUX argmin selection.
// ---------------------------------------------------------------------------
template <int NSRC, int M, int STAGE, int CAP>
__global__ __launch_bounds__(256) void kneigh() {
    const float* src  = (STAGE == 1) ? g_pn : g_q1;
    const float* qsrc = (STAGE == 1) ? g_q1 : g_q2;
    int* nidx         = (STAGE == 1) ? g_nidx1 : g_nidx2;
    const float r2    = (STAGE == 1) ? (float)(0.15 * 0.15) : (float)(0.3 * 0.3);

    extern __shared__ __align__(16) char dynbuf[];
    float4* spts = (float4*)dynbuf;                         // [NSRC]
    unsigned short* cand = (unsigned short*)(spts + NSRC);  // [8][CAP]

    int tid = threadIdx.x;
    int lane = tid & 31, w = tid >> 5;
    int tilesPerPatch = M / 16;
    int p    = blockIdx.x / tilesPerPatch;
    int tile = blockIdx.x % tilesPerPatch;
    const float* base = src + (size_t)p * NSRC * 3;

    for (int i = tid; i < NSRC; i += 256) {
        spts[i] = make_float4(base[i * 3 + 0], base[i * 3 + 1], base[i * 3 + 2], 0.0f);
    }
    __syncthreads();

    unsigned short* mycand = cand + (size_t)w * CAP;
    unsigned lmask = (1u << lane) - 1u;

    for (int g = 0; g < 2; g++) {
        int center = p * M + tile * 16 + g * 8 + w;
        float qx = qsrc[center * 3 + 0];
        float qy = qsrc[center * 3 + 1];
        float qz = qsrc[center * 3 + 2];

        int cnt = 0;
        for (int i = lane; i < NSRC; i += 32) {
            float4 pt = spts[i];
            float d2 = d2_exact(pt.x, pt.y, pt.z, qx, qy, qz);
            bool in = (d2 <= r2);
            unsigned mk = __ballot_sync(0xffffffffu, in);
            if (in) {
                int pos = cnt + __popc(mk & lmask);
                if (pos < CAP) mycand[pos] = (unsigned short)i;
            }
            cnt += __popc(mk);
        }

        if (cnt <= 32) {
            int v = (lane < cnt) ? (int)mycand[lane] : -1;
            nidx[center * KNB + lane] = v;
        } else if (cnt <= CAP) {
            unsigned last_d2 = 0, last_idx = 0;
            for (int k = 0; k < KNB; k++) {
                unsigned bd2 = 0xFFFFFFFFu, bidx = 0xFFFFFFFFu;
                for (int i = lane; i < cnt; i += 32) {
                    unsigned idx = mycand[i];
                    float4 pt = spts[idx];
                    float d2 = d2_exact(pt.x, pt.y, pt.z, qx, qy, qz);
                    unsigned db = __float_as_uint(d2);
                    bool ok = (k == 0) || (db > last_d2) ||
                              (db == last_d2 && idx > last_idx);
                    if (ok && db < bd2) { bd2 = db; bidx = idx; }
                }
                unsigned gmin = __reduce_min_sync(0xffffffffu, bd2);
                unsigned cd = (bd2 == gmin) ? bidx : 0xFFFFFFFFu;
                unsigned gidx = __reduce_min_sync(0xffffffffu, cd);
                if (lane == 0) nidx[center * KNB + k] = (int)gidx;
                last_d2 = gmin; last_idx = gidx;
            }
        } else {
            unsigned last_d2 = 0, last_idx = 0;
            for (int k = 0; k < KNB; k++) {
                unsigned bd2 = 0xFFFFFFFFu, bidx = 0xFFFFFFFFu;
                for (int i = lane; i < NSRC; i += 32) {
                    float4 pt = spts[i];
                    float d2 = d2_exact(pt.x, pt.y, pt.z, qx, qy, qz);
                    if (d2 <= r2) {
                        unsigned db = __float_as_uint(d2);
                        unsigned idx = (unsigned)i;
                        bool ok = (k == 0) || (db > last_d2) ||
                                  (db == last_d2 && idx > last_idx);
                        if (ok && db < bd2) { bd2 = db; bidx = idx; }
                    }
                }
                unsigned gmin = __reduce_min_sync(0xffffffffu, bd2);
                unsigned cd = (bd2 == gmin) ? bidx : 0xFFFFFFFFu;
                unsigned gidx = __reduce_min_sync(0xffffffffu, cd);
                if (lane == 0) nidx[center * KNB + k] = (int)gidx;
                last_d2 = gmin; last_idx = gidx;
            }
        }
    }
}

// ---------------------------------------------------------------------------
// Stage-1 MLP: layer 1 via precomputed Ypn (gather + subtract + relu),
// layer 2 = 4ch x 8k register-blocked f32x2 (unchanged from round 10).
// 2 groups of 128 threads; 8 centers/block.
// ---------------------------------------------------------------------------
__global__ __launch_bounds__(256) void kmlp1(
    const float* __restrict__ W1a, const float* __restrict__ b1a,
    const float* __restrict__ W1b, const float* __restrict__ b1b) {
    extern __shared__ __align__(16) float sm1[];
    float* sWb = sm1;                  // 64*128
    float* sbb = sWb + 64 * 128;       // 128
    float* sh1A = sbb + 128;           // [2][64*32]
    __shared__ int   sj[2][32];
    __shared__ float sq[2][3];

    int tid = threadIdx.x;
    int grp = tid >> 7, t = tid & 127;
    float* sh1 = sh1A + grp * 64 * 32;

    for (int i = tid; i < 64 * 128; i += 256) sWb[i] = W1b[i];
    if (tid < 128) sbb[tid] = b1b[tid];

    int kg = t & 3, k0 = kg * 8;
    int c0 = (t >> 2) * 4;             // layer-2 channels
    int c1 = (t >> 2) * 2;             // layer-1 channels (0..62)

    // center-invariant layer-1 W rows (for cvec)
    float2 w3[3];
    #pragma unroll
    for (int d = 0; d < 3; d++) w3[d] = __ldg((const float2*)&W1a[(3 + d) * 64 + c1]);

    for (int cc = 0; cc < 4; cc++) {
        __syncthreads();
        int center = blockIdx.x * 8 + cc * 2 + grp;
        int p = center >> 9;
        if (t < 32) sj[grp][t] = g_nidx1[center * KNB + t];
        if (t < 3)  sq[grp][t] = g_q1[center * 3 + t];
        __syncthreads();

        // ---- layer 1: h = relu(Ypn[j] - W1a[3:6]^T q), 2ch x 8k ----
        {
            float cvx = 0.0f, cvy = 0.0f;
            #pragma unroll
            for (int d = 0; d < 3; d++) {
                cvx += w3[d].x * sq[grp][d];
                cvy += w3[d].y * sq[grp][d];
            }
            float2 r[8];
            #pragma unroll
            for (int kk = 0; kk < 8; kk++) {
                int j = sj[grp][k0 + kk];
                int jj = (j < 0) ? 0 : j;
                r[kk] = __ldg((const float2*)&g_ypn[((size_t)p * NN + jj) * 64 + c1]);
            }
            float4 lo, hi;
            lo.x = fmaxf(r[0].x - cvx, 0.0f); lo.y = fmaxf(r[1].x - cvx, 0.0f);
            lo.z = fmaxf(r[2].x - cvx, 0.0f); lo.w = fmaxf(r[3].x - cvx, 0.0f);
            hi.x = fmaxf(r[4].x - cvx, 0.0f); hi.y = fmaxf(r[5].x - cvx, 0.0f);
            hi.z = fmaxf(r[6].x - cvx, 0.0f); hi.w = fmaxf(r[7].x - cvx, 0.0f);
            *(float4*)&sh1[c1 * 32 + k0]     = lo;
            *(float4*)&sh1[c1 * 32 + k0 + 4] = hi;
            lo.x = fmaxf(r[0].y - cvy, 0.0f); lo.y = fmaxf(r[1].y - cvy, 0.0f);
            lo.z = fmaxf(r[2].y - cvy, 0.0f); lo.w = fmaxf(r[3].y - cvy, 0.0f);
            hi.x = fmaxf(r[4].y - cvy, 0.0f); hi.y = fmaxf(r[5].y - cvy, 0.0f);
            hi.z = fmaxf(r[6].y - cvy, 0.0f); hi.w = fmaxf(r[7].y - cvy, 0.0f);
            *(float4*)&sh1[(c1 + 1) * 32 + k0]     = lo;
            *(float4*)&sh1[(c1 + 1) * 32 + k0 + 4] = hi;
        }
        __syncthreads();

        // ---- layer 2: 64 -> 128, 4ch x 8k ----
        {
            u64 acc[16];
            #pragma unroll
            for (int q = 0; q < 16; q++) acc[q] = 0ull;
            #pragma unroll 4
            for (int i = 0; i < 64; i++) {
                float4 w4 = *(const float4*)&sWb[i * 128 + c0];
                const ulonglong2* hp = (const ulonglong2*)&sh1[i * 32 + k0];
                ulonglong2 ha = hp[0], hb = hp[1];
                u64 w0 = dup2(w4.x), w1 = dup2(w4.y), w2 = dup2(w4.z), w3p = dup2(w4.w);
                acc[0]  = fma2(ha.x, w0, acc[0]);  acc[1]  = fma2(ha.y, w0, acc[1]);
                acc[2]  = fma2(hb.x, w0, acc[2]);  acc[3]  = fma2(hb.y, w0, acc[3]);
                acc[4]  = fma2(ha.x, w1, acc[4]);  acc[5]  = fma2(ha.y, w1, acc[5]);
                acc[6]  = fma2(hb.x, w1, acc[6]);  acc[7]  = fma2(hb.y, w1, acc[7]);
                acc[8]  = fma2(ha.x, w2, acc[8]);  acc[9]  = fma2(ha.y, w2, acc[9]);
                acc[10] = fma2(hb.x, w2, acc[10]); acc[11] = fma2(hb.y, w2, acc[11]);
                acc[12] = fma2(ha.x, w3p, acc[12]); acc[13] = fma2(ha.y, w3p, acc[13]);
                acc[14] = fma2(hb.x, w3p, acc[14]); acc[15] = fma2(hb.y, w3p, acc[15]);
            }
            float4 b4 = *(const float4*)&sbb[c0];
            float bias[4] = {b4.x, b4.y, b4.z, b4.w};
            #pragma unroll
            for (int ci = 0; ci < 4; ci++) {
                float b = bias[ci];
                float m = -FLT_MAX;
                #pragma unroll
                for (int qq = 0; qq < 4; qq++) {
                    float2 f = unpk(acc[ci * 4 + qq]);
                    if (sj[grp][k0 + 2 * qq + 0] >= 0) m = fmaxf(m, fmaxf(f.x + b, 0.0f));
                    if (sj[grp][k0 + 2 * qq + 1] >= 0) m = fmaxf(m, fmaxf(f.y + b, 0.0f));
                }
                m = fmaxf(m, __shfl_xor_sync(0xffffffffu, m, 1));
                m = fmaxf(m, __shfl_xor_sync(0xffffffffu, m, 2));
                if (kg == 0) g_x1[(size_t)center * 128 + c0 + ci] = m;
            }
        }
    }
}

// ---------------------------------------------------------------------------
// Stage-2 MLP: layer A via precomputed YZ (gather + subtract + relu),
// layer B unchanged (4ch x 8k, 2 passes). One center per 256-thread block.
// ---------------------------------------------------------------------------
__global__ __launch_bounds__(256) void kmlp2(
    const float* __restrict__ W2a, const float* __restrict__ b2a,
    const float* __restrict__ W2b, const float* __restrict__ b2b,
    float* __restrict__ out) {
    extern __shared__ __align__(16) float smem2[];
    float* sh1 = smem2;                // [256][32]
    __shared__ int   sj[32];
    __shared__ float sq[3];
    int t = threadIdx.x;
    int center = blockIdx.x;
    int p = center >> 7;
    if (t < 32) sj[t] = g_nidx2[center * KNB + t];
    if (t < 3) {
        float qv = g_q2[center * 3 + t];
        sq[t] = qv;
        out[OFF_Q2 + center * 3 + t] = qv;
    }
    __syncthreads();

    int kg = t & 3, k0 = kg * 8;
    int c0 = (t >> 2) * 4;             // 0..252

    // ---- layer A: h1 = relu(YZ[j] - W2a[128:131]^T q2), 4ch x 8k ----
    {
        float4 cv = make_float4(0.0f, 0.0f, 0.0f, 0.0f);
        #pragma unroll
        for (int d = 0; d < 3; d++) {
            float4 w = __ldg((const float4*)&W2a[(128 + d) * 256 + c0]);
            float s = sq[d];
            cv.x += w.x * s; cv.y += w.y * s; cv.z += w.z * s; cv.w += w.w * s;
        }
        float4 r[8];
        #pragma unroll
        for (int kk = 0; kk < 8; kk++) {
            int j = sj[k0 + kk];
            int jj = (j < 0) ? 0 : j;
            r[kk] = __ldg((const float4*)&g_yz[((size_t)p * M1 + jj) * 256 + c0]);
        }
        #pragma unroll
        for (int kk = 0; kk < 8; kk++) {
            r[kk].x = fmaxf(r[kk].x - cv.x, 0.0f);
            r[kk].y = fmaxf(r[kk].y - cv.y, 0.0f);
            r[kk].z = fmaxf(r[kk].z - cv.z, 0.0f);
            r[kk].w = fmaxf(r[kk].w - cv.w, 0.0f);
        }
        float4 lo, hi;
        lo = make_float4(r[0].x, r[1].x, r[2].x, r[3].x);
        hi = make_float4(r[4].x, r[5].x, r[6].x, r[7].x);
        *(float4*)&sh1[(c0 + 0) * 32 + k0] = lo;
        *(float4*)&sh1[(c0 + 0) * 32 + k0 + 4] = hi;
        lo = make_float4(r[0].y, r[1].y, r[2].y, r[3].y);
        hi = make_float4(r[4].y, r[5].y, r[6].y, r[7].y);
        *(float4*)&sh1[(c0 + 1) * 32 + k0] = lo;
        *(float4*)&sh1[(c0 + 1) * 32 + k0 + 4] = hi;
        lo = make_float4(r[0].z, r[1].z, r[2].z, r[3].z);
        hi = make_float4(r[4].z, r[5].z, r[6].z, r[7].z);
        *(float4*)&sh1[(c0 + 2) * 32 + k0] = lo;
        *(float4*)&sh1[(c0 + 2) * 32 + k0 + 4] = hi;
        lo = make_float4(r[0].w, r[1].w, r[2].w, r[3].w);
        hi = make_float4(r[4].w, r[5].w, r[6].w, r[7].w);
        *(float4*)&sh1[(c0 + 3) * 32 + k0] = lo;
        *(float4*)&sh1[(c0 + 3) * 32 + k0 + 4] = hi;
    }
    __syncthreads();

    // ---- layer B: 256 -> 384 (2 passes; second pass half-active) ----
    #pragma unroll
    for (int pass = 0; pass < 2; pass++) {
        int cb = pass * 256 + c0;
        if (cb < 384) {
            u64 acc[16];
            #pragma unroll
            for (int q = 0; q < 16; q++) acc[q] = 0ull;
            #pragma unroll 4
            for (int i = 0; i < 256; i++) {
                float4 w4 = __ldg((const float4*)&W2b[i * 384 + cb]);
                const ulonglong2* hp = (const ulonglong2*)&sh1[i * 32 + k0];
                ulonglong2 ha = hp[0], hb = hp[1];
                u64 w0 = dup2(w4.x), w1 = dup2(w4.y), w2 = dup2(w4.z), w3 = dup2(w4.w);
                acc[0]  = fma2(ha.x, w0, acc[0]);  acc[1]  = fma2(ha.y, w0, acc[1]);
                acc[2]  = fma2(hb.x, w0, acc[2]);  acc[3]  = fma2(hb.y, w0, acc[3]);
                acc[4]  = fma2(ha.x, w1, acc[4]);  acc[5]  = fma2(ha.y, w1, acc[5]);
                acc[6]  = fma2(hb.x, w1, acc[6]);  acc[7]  = fma2(hb.y, w1, acc[7]);
                acc[8]  = fma2(ha.x, w2, acc[8]);  acc[9]  = fma2(ha.y, w2, acc[9]);
                acc[10] = fma2(hb.x, w2, acc[10]); acc[11] = fma2(hb.y, w2, acc[11]);
                acc[12] = fma2(ha.x, w3, acc[12]); acc[13] = fma2(ha.y, w3, acc[13]);
                acc[14] = fma2(hb.x, w3, acc[14]); acc[15] = fma2(hb.y, w3, acc[15]);
            }
            float4 b4 = __ldg((const float4*)&b2b[cb]);
            float bias[4] = {b4.x, b4.y, b4.z, b4.w};
            #pragma unroll
            for (int ci = 0; ci < 4; ci++) {
                float b = bias[ci];
                float m = -FLT_MAX;
                #pragma unroll
                for (int qq = 0; qq < 4; qq++) {
                    float2 f = unpk(acc[ci * 4 + qq]);
                    if (sj[k0 + 2 * qq + 0] >= 0) m = fmaxf(m, fmaxf(f.x + b, 0.0f));
                    if (sj[k0 + 2 * qq + 1] >= 0) m = fmaxf(m, fmaxf(f.y + b, 0.0f));
                }
                m = fmaxf(m, __shfl_xor_sync(0xffffffffu, m, 1));
                m = fmaxf(m, __shfl_xor_sync(0xffffffffu, m, 2));
                if (kg == 0) out[OFF_X2 + (size_t)center * 384 + cb + ci] = m;
            }
        }
    }
}

// ---------------------------------------------------------------------------
// Stage-3 MLP: feat[387] -> 512 -> 768; 16 centers/block, 256 threads.
// Register-blocked 4 channels x 4 centers per thread. (unchanged)
// ---------------------------------------------------------------------------
__global__ __launch_bounds__(256) void kmlp3(
    const float* __restrict__ W3a, const float* __restrict__ b3a,
    const float* __restrict__ W3b, const float* __restrict__ b3b,
    float* __restrict__ out) {
    extern __shared__ __align__(16) char smem3[];
    float* sfeat = (float*)smem3;          // [387][16]
    float* sh1   = sfeat + 387 * 16;       // [512][16]
    int t = threadIdx.x;
    int base = blockIdx.x * 16;
    int p = base >> 7;

    for (int o = t; o < 387 * 16; o += 256) {
        int cen = o & 15, i = o >> 4;
        int center = base + cen;
        float v = (i < 384) ? out[OFF_X2 + (size_t)center * 384 + i]
                            : out[OFF_Q2 + center * 3 + (i - 384)];
        sfeat[i * 16 + cen] = v;
    }
    __syncthreads();

    int eg = t & 3, e0 = eg * 4;
    int c0 = (t >> 2) * 4;                  // 0..252

    // ---- layer A: 387 -> 512 (2 passes) ----
    #pragma unroll
    for (int pass = 0; pass < 2; pass++) {
        int ca = pass * 256 + c0;           // < 512
        u64 acc[8];
        #pragma unroll
        for (int q = 0; q < 8; q++) acc[q] = 0ull;
        #pragma unroll 4
        for (int i = 0; i < 387; i++) {
            float4 w4 = __ldg((const float4*)&W3a[i * 512 + ca]);
            ulonglong2 h = *(const ulonglong2*)&sfeat[i * 16 + e0];
            u64 w0 = dup2(w4.x), w1 = dup2(w4.y), w2 = dup2(w4.z), w3 = dup2(w4.w);
            acc[0] = fma2(h.x, w0, acc[0]); acc[1] = fma2(h.y, w0, acc[1]);
            acc[2] = fma2(h.x, w1, acc[2]); acc[3] = fma2(h.y, w1, acc[3]);
            acc[4] = fma2(h.x, w2, acc[4]); acc[5] = fma2(h.y, w2, acc[5]);
            acc[6] = fma2(h.x, w3, acc[6]); acc[7] = fma2(h.y, w3, acc[7]);
        }
        float4 b4 = __ldg((const float4*)&b3a[ca]);
        float bias[4] = {b4.x, b4.y, b4.z, b4.w};
        #pragma unroll
        for (int ci = 0; ci < 4; ci++) {
            float b = bias[ci];
            float2 f0 = unpk(acc[ci * 2 + 0]);
            float2 f1 = unpk(acc[ci * 2 + 1]);
            float4 s;
            s.x = fmaxf(f0.x + b, 0.0f); s.y = fmaxf(f0.y + b, 0.0f);
            s.z = fmaxf(f1.x + b, 0.0f); s.w = fmaxf(f1.y + b, 0.0f);
            *(float4*)&sh1[(ca + ci) * 16 + e0] = s;
        }
    }
    __syncthreads();

    // ---- layer B: 512 -> 768 (3 passes) + global max ----
    #pragma unroll
    for (int pass = 0; pass < 3; pass++) {
        int cb = pass * 256 + c0;           // < 768
        u64 acc[8];
        #pragma unroll
        for (int q = 0; q < 8; q++) acc[q] = 0ull;
        #pragma unroll 4
        for (int i = 0; i < 512; i++) {
            float4 w4 = __ldg((const float4*)&W3b[i * 768 + cb]);
            ulonglong2 h = *(const ulonglong2*)&sh1[i * 16 + e0];
            u64 w0 = dup2(w4.x), w1 = dup2(w4.y), w2 = dup2(w4.z), w3 = dup2(w4.w);
            acc[0] = fma2(h.x, w0, acc[0]); acc[1] = fma2(h.y, w0, acc[1]);
            acc[2] = fma2(h.x, w1, acc[2]); acc[3] = fma2(h.y, w1, acc[3]);
            acc[4] = fma2(h.x, w2, acc[4]); acc[5] = fma2(h.y, w2, acc[5]);
            acc[6] = fma2(h.x, w3, acc[6]); acc[7] = fma2(h.y, w3, acc[7]);
        }
        float4 b4 = __ldg((const float4*)&b3b[cb]);
        float bias[4] = {b4.x, b4.y, b4.z, b4.w};
        #pragma unroll
        for (int ci = 0; ci < 4; ci++) {
            float b = bias[ci];
            float2 f0 = unpk(acc[ci * 2 + 0]);
            float2 f1 = unpk(acc[ci * 2 + 1]);
            float m = fmaxf(fmaxf(f0.x + b, 0.0f), fmaxf(f0.y + b, 0.0f));
            m = fmaxf(m, fmaxf(f1.x + b, 0.0f));
            m = fmaxf(m, fmaxf(f1.y + b, 0.0f));
            m = fmaxf(m, __shfl_xor_sync(0xffffffffu, m, 1));
            m = fmaxf(m, __shfl_xor_sync(0xffffffffu, m, 2));
            if (eg == 0)
                atomicMax((int*)&out[OFF_XG + p * 768 + cb + ci], __float_as_int(m));
        }
    }
}

// ---------------------------------------------------------------------------
extern "C" void kernel_launch(void* const* d_in, const int* in_sizes, int n_in,
                              void* d_out, int out_size) {
    const float* pos = (const float*)d_in[0];
    const float* W1a = (const float*)d_in[2];
    const float* b1a = (const float*)d_in[3];
    const float* W1b = (const float*)d_in[4];
    const float* b1b = (const float*)d_in[5];
    const float* W2a = (const float*)d_in[6];
    const float* b2a = (const float*)d_in[7];
    const float* W2b = (const float*)d_in[8];
    const float* b2b = (const float*)d_in[9];
    const float* W3a = (const float*)d_in[10];
    const float* b3a = (const float*)d_in[11];
    const float* W3b = (const float*)d_in[12];
    const float* b3b = (const float*)d_in[13];
    float* out = (float*)d_out;

    const int CAP1 = 1024, CAP2 = 512;
    const int NEIGH1_SMEM = NN * 16 + 8 * CAP1 * 2;      // 49152
    const int NEIGH2_SMEM = M1 * 16 + 8 * CAP2 * 2;      // 16384
    const int MLP1_SMEM   = (64 * 128 + 128 + 2 * 64 * 32) * 4;  // 49664
    const int MLP2_SMEM   = 256 * 32 * 4;                // 32768
    const int MLP3_SMEM   = (387 * 16 + 512 * 16) * 4;   // 57536
    const int PRE2_SMEM   = 131 * 32 * 4;                // 16768
    cudaFuncSetAttribute(kneigh<NN, M1, 1, CAP1>,
                         cudaFuncAttributeMaxDynamicSharedMemorySize, NEIGH1_SMEM);
    cudaFuncSetAttribute(kneigh<M1, M2, 2, CAP2>,
                         cudaFuncAttributeMaxDynamicSharedMemorySize, NEIGH2_SMEM);
    cudaFuncSetAttribute(kmlp1,
                         cudaFuncAttributeMaxDynamicSharedMemorySize, MLP1_SMEM);
    cudaFuncSetAttribute(kmlp2,
                         cudaFuncAttributeMaxDynamicSharedMemorySize, MLP2_SMEM);
    cudaFuncSetAttribute(kmlp3,
                         cudaFuncAttributeMaxDynamicSharedMemorySize, MLP3_SMEM);
    cudaFuncSetAttribute(kpre2,
                         cudaFuncAttributeMaxDynamicSharedMemorySize, PRE2_SMEM);

    knorm<<<PP, 256>>>(pos, out);                                        // 0
    kfps<NN, M1, 1><<<PP, 256>>>();                                      // 1
    kpre1<<<PP * NN * 16 / 256, 256>>>(W1a, b1a);                        // 2
    kneigh<NN, M1, 1, CAP1><<<PP * M1 / 16, 256, NEIGH1_SMEM>>>();       // 3 <- profiled
    kmlp1<<<PP * M1 / 8, 256, MLP1_SMEM>>>(W1a, b1a, W1b, b1b);          // 4
    kfps<M1, M2, 2><<<PP, 256>>>();                                      // 5
    kneigh<M1, M2, 2, CAP2><<<PP * M2 / 16, 256, NEIGH2_SMEM>>>();       // 6
    kpre2<<<PP * M1 / 32, 256, PRE2_SMEM>>>(W2a, b2a);                   // 7
    kmlp2<<<PP * M2, 256, MLP2_SMEM>>>(W2a, b2a, W2b, b2b, out);         // 8
    kinit<<<192, 256>>>(out);                                            // 9
    kmlp3<<<PP * M2 / 16, 256, MLP3_SMEM>>>(W3a, b3a, W3b, b3b, out);    // 10
}